// round 2
// baseline (speedup 1.0000x reference)
#include <cuda_runtime.h>
#include <cuda_bf16.h>
#include <cstddef>

// ---------------------------------------------------------------------------
// Problem constants
// ---------------------------------------------------------------------------
#define B     4
#define N1    2048
#define N2    2048
#define D     1024
#define HEADS 8
#define DHEAD 64
#define INNER (HEADS * DHEAD)     // 512
#define NKV   (N1 + N2)           // 4096

// Scratch (device globals — no allocation allowed)
__device__ float g_q1[(size_t)B * N1 * INNER];   // 16 MB
__device__ float g_k [(size_t)B * NKV * INNER];  // 32 MB
__device__ float g_v [(size_t)B * NKV * INNER];  // 32 MB
__device__ float g_ao[(size_t)B * N1 * INNER];   // 16 MB

// ---------------------------------------------------------------------------
// Tiled SGEMM: C[b] = A[b] @ W (+bias), 64x64 tile, BK=16, 256 threads,
// 4x4 micro-tile per thread. A: [M,K] row-major per batch, W: [K,N] shared.
// ---------------------------------------------------------------------------
__global__ __launch_bounds__(256)
void sgemm64(const float* __restrict__ A, const float* __restrict__ W,
             float* __restrict__ C, const float* __restrict__ bias,
             int M, int N, int K,
             size_t astride, size_t cstride, size_t coff)
{
    __shared__ float As[16][64];   // [k][m]
    __shared__ float Bs[16][64];   // [k][n]

    const float* Ab = A + (size_t)blockIdx.z * astride;
    float*       Cb = C + (size_t)blockIdx.z * cstride + coff;

    const int row0 = blockIdx.y * 64;
    const int col0 = blockIdx.x * 64;
    const int tid  = threadIdx.x;
    const int ty   = tid >> 4;          // 0..15
    const int tx   = tid & 15;          // 0..15

    const int ar = tid >> 2;            // 0..63 (m within tile)
    const int ac = (tid & 3) << 2;      // 0,4,8,12 (k)
    const int br = tid >> 4;            // 0..15 (k)
    const int bc = (tid & 15) << 2;     // 0..60 (n)

    float acc[4][4] = {};

    for (int k0 = 0; k0 < K; k0 += 16) {
        float4 av = *(const float4*)&Ab[(size_t)(row0 + ar) * K + k0 + ac];
        As[ac + 0][ar] = av.x;
        As[ac + 1][ar] = av.y;
        As[ac + 2][ar] = av.z;
        As[ac + 3][ar] = av.w;
        *(float4*)&Bs[br][bc] = *(const float4*)&W[(size_t)(k0 + br) * N + col0 + bc];
        __syncthreads();

        #pragma unroll
        for (int kk = 0; kk < 16; kk++) {
            float4 a = *(const float4*)&As[kk][ty << 2];
            float4 b = *(const float4*)&Bs[kk][tx << 2];
            acc[0][0] += a.x * b.x; acc[0][1] += a.x * b.y; acc[0][2] += a.x * b.z; acc[0][3] += a.x * b.w;
            acc[1][0] += a.y * b.x; acc[1][1] += a.y * b.y; acc[1][2] += a.y * b.z; acc[1][3] += a.y * b.w;
            acc[2][0] += a.z * b.x; acc[2][1] += a.z * b.y; acc[2][2] += a.z * b.z; acc[2][3] += a.z * b.w;
            acc[3][0] += a.w * b.x; acc[3][1] += a.w * b.y; acc[3][2] += a.w * b.z; acc[3][3] += a.w * b.w;
        }
        __syncthreads();
    }

    float4 bv = make_float4(0.f, 0.f, 0.f, 0.f);
    if (bias) bv = *(const float4*)&bias[col0 + (tx << 2)];

    #pragma unroll
    for (int ii = 0; ii < 4; ii++) {
        int row = row0 + (ty << 2) + ii;
        float4 o;
        o.x = acc[ii][0] + bv.x;
        o.y = acc[ii][1] + bv.y;
        o.z = acc[ii][2] + bv.z;
        o.w = acc[ii][3] + bv.w;
        *(float4*)&Cb[(size_t)row * N + col0 + (tx << 2)] = o;
    }
}

// ---------------------------------------------------------------------------
// Flash attention (fp32): one block per (q-tile of 64 rows, head, batch).
// Online softmax, O accumulators in registers (4x4 per thread).
// Smem layouts: Qt[d][i]  Kt[d][j]  Vs[j][d]  Ps[j][i], PAD=68.
// ---------------------------------------------------------------------------
#define PAD 68

__global__ __launch_bounds__(256)
void flash_attn(const float* __restrict__ q,
                const float* __restrict__ kc,
                const float* __restrict__ vc,
                float* __restrict__ ao)
{
    extern __shared__ float sm[];
    float* Qt   = sm;                 // 64*PAD
    float* Kt   = Qt + 64 * PAD;
    float* Vs   = Kt + 64 * PAD;
    float* Ps   = Vs + 64 * PAD;
    float* mrow = Ps + 64 * PAD;      // 64
    float* lrow = mrow + 64;          // 64
    float* arow = lrow + 64;          // 64

    const int b  = blockIdx.z;
    const int h  = blockIdx.y;
    const int qt = blockIdx.x;
    const int tid = threadIdx.x;
    const int ty = tid >> 4;          // 0..15
    const int tx = tid & 15;          // 0..15
    const float scale = 0.125f;       // 1/sqrt(64)

    const int li = tid >> 2;          // 0..63 : row handled by this thread
    const int lc = (tid & 3) << 4;    // 0,16,32,48 : d-chunk base

    // Load FULL Q tile (pre-scaled): 64 rows x 64 dims (4 float4 per thread)
    {
        const float* qb = q + ((size_t)b * N1 + (size_t)qt * 64) * INNER + h * DHEAD;
        #pragma unroll
        for (int c = 0; c < 4; c++) {
            int d4 = lc + (c << 2);
            float4 v = *(const float4*)&qb[(size_t)li * INNER + d4];
            Qt[(d4 + 0) * PAD + li] = v.x * scale;
            Qt[(d4 + 1) * PAD + li] = v.y * scale;
            Qt[(d4 + 2) * PAD + li] = v.z * scale;
            Qt[(d4 + 3) * PAD + li] = v.w * scale;
        }
    }
    if (tid < 64) { mrow[tid] = -1e30f; lrow[tid] = 0.f; }

    float acc[4][4] = {};   // O[i = ty*4+ii][d = tx*4+jj]

    const float* kb = kc + (size_t)b * NKV * INNER + h * DHEAD;
    const float* vb = vc + (size_t)b * NKV * INNER + h * DHEAD;

    for (int j0 = 0; j0 < NKV; j0 += 64) {
        __syncthreads();   // previous iteration's readers of Kt/Vs/Ps done

        // Load FULL K and V tiles (64x64 each; 4 float4 per thread per tile)
        {
            const float* krow = &kb[(size_t)(j0 + li) * INNER];
            const float* vrow = &vb[(size_t)(j0 + li) * INNER];
            #pragma unroll
            for (int c = 0; c < 4; c++) {
                int d4 = lc + (c << 2);
                float4 kv = *(const float4*)&krow[d4];
                Kt[(d4 + 0) * PAD + li] = kv.x;
                Kt[(d4 + 1) * PAD + li] = kv.y;
                Kt[(d4 + 2) * PAD + li] = kv.z;
                Kt[(d4 + 3) * PAD + li] = kv.w;
                float4 vv = *(const float4*)&vrow[d4];
                *(float4*)&Vs[li * PAD + d4] = vv;
            }
        }
        __syncthreads();

        // S^T: Ps[j][i] = sum_d K[j][d] * Q[i][d]   (j = ty*4.., i = tx*4..)
        {
            float s[4][4] = {};
            #pragma unroll 16
            for (int d = 0; d < 64; d++) {
                float4 a  = *(const float4*)&Kt[d * PAD + (ty << 2)];
                float4 b4 = *(const float4*)&Qt[d * PAD + (tx << 2)];
                s[0][0] += a.x * b4.x; s[0][1] += a.x * b4.y; s[0][2] += a.x * b4.z; s[0][3] += a.x * b4.w;
                s[1][0] += a.y * b4.x; s[1][1] += a.y * b4.y; s[1][2] += a.y * b4.z; s[1][3] += a.y * b4.w;
                s[2][0] += a.z * b4.x; s[2][1] += a.z * b4.y; s[2][2] += a.z * b4.z; s[2][3] += a.z * b4.w;
                s[3][0] += a.w * b4.x; s[3][1] += a.w * b4.y; s[3][2] += a.w * b4.z; s[3][3] += a.w * b4.w;
            }
            #pragma unroll
            for (int jj = 0; jj < 4; jj++) {
                float4 o = make_float4(s[jj][0], s[jj][1], s[jj][2], s[jj][3]);
                *(float4*)&Ps[((ty << 2) + jj) * PAD + (tx << 2)] = o;
            }
        }
        __syncthreads();

        // Online softmax along column i of Ps (thread i<64 owns query row i)
        if (tid < 64) {
            int i = tid;
            float mo = mrow[i];
            float mt = mo;
            #pragma unroll 8
            for (int j = 0; j < 64; j++) {
                float v = Ps[j * PAD + i];
                mt = fmaxf(mt, v);
            }
            float alpha = __expf(mo - mt);
            float ls = 0.f;
            #pragma unroll 8
            for (int j = 0; j < 64; j++) {
                float p = __expf(Ps[j * PAD + i] - mt);
                Ps[j * PAD + i] = p;
                ls += p;
            }
            mrow[i] = mt;
            lrow[i] = lrow[i] * alpha + ls;
            arow[i] = alpha;
        }
        __syncthreads();

        // Rescale O and accumulate: O[i][d] += sum_j Ps[j][i] * V[j][d]
        {
            float a0 = arow[(ty << 2) + 0];
            float a1 = arow[(ty << 2) + 1];
            float a2 = arow[(ty << 2) + 2];
            float a3 = arow[(ty << 2) + 3];
            #pragma unroll
            for (int jj = 0; jj < 4; jj++) {
                acc[0][jj] *= a0;
                acc[1][jj] *= a1;
                acc[2][jj] *= a2;
                acc[3][jj] *= a3;
            }
            #pragma unroll 16
            for (int j = 0; j < 64; j++) {
                float4 a  = *(const float4*)&Ps[j * PAD + (ty << 2)];
                float4 v4 = *(const float4*)&Vs[j * PAD + (tx << 2)];
                acc[0][0] += a.x * v4.x; acc[0][1] += a.x * v4.y; acc[0][2] += a.x * v4.z; acc[0][3] += a.x * v4.w;
                acc[1][0] += a.y * v4.x; acc[1][1] += a.y * v4.y; acc[1][2] += a.y * v4.z; acc[1][3] += a.y * v4.w;
                acc[2][0] += a.z * v4.x; acc[2][1] += a.z * v4.y; acc[2][2] += a.z * v4.z; acc[2][3] += a.z * v4.w;
                acc[3][0] += a.w * v4.x; acc[3][1] += a.w * v4.y; acc[3][2] += a.w * v4.z; acc[3][3] += a.w * v4.w;
            }
        }
    }

    // Normalize and write: ao[b, qt*64 + i, h*64 + d]
    {
        float* ab = ao + ((size_t)b * N1 + (size_t)qt * 64) * INNER + h * DHEAD;
        #pragma unroll
        for (int ii = 0; ii < 4; ii++) {
            int i = (ty << 2) + ii;
            float linv = 1.0f / lrow[i];
            float4 o;
            o.x = acc[ii][0] * linv;
            o.y = acc[ii][1] * linv;
            o.z = acc[ii][2] * linv;
            o.w = acc[ii][3] * linv;
            *(float4*)&ab[(size_t)i * INNER + (tx << 2)] = o;
        }
    }
}

// ---------------------------------------------------------------------------
// Launch
// ---------------------------------------------------------------------------
extern "C" void kernel_launch(void* const* d_in, const int* in_sizes, int n_in,
                              void* d_out, int out_size)
{
    (void)in_sizes; (void)n_in; (void)out_size;

    const float* x1  = (const float*)d_in[0];
    const float* x2  = (const float*)d_in[1];
    const float* Wq1 = (const float*)d_in[2];
    const float* Wk1 = (const float*)d_in[3];
    const float* Wv1 = (const float*)d_in[4];
    const float* Wk2 = (const float*)d_in[5];
    const float* Wv2 = (const float*)d_in[6];
    const float* Wo  = (const float*)d_in[7];
    const float* bo  = (const float*)d_in[8];
    float* out = (float*)d_out;

    float *q1, *kbuf, *vbuf, *aobuf;
    cudaGetSymbolAddress((void**)&q1,    g_q1);
    cudaGetSymbolAddress((void**)&kbuf,  g_k);
    cudaGetSymbolAddress((void**)&vbuf,  g_v);
    cudaGetSymbolAddress((void**)&aobuf, g_ao);

    const size_t xs  = (size_t)N1 * D;       // per-batch x stride (N1==N2)
    const size_t qs  = (size_t)N1 * INNER;   // per-batch q1 / ao stride
    const size_t kvs = (size_t)NKV * INNER;  // per-batch kv stride
    const size_t off2 = (size_t)N1 * INNER;  // concat offset for the x2 half

    dim3 gproj(INNER / 64, N1 / 64, B);      // (8, 32, 4)
    dim3 gout (D / 64,     N1 / 64, B);      // (16, 32, 4)

    // 1) Projections
    sgemm64<<<gproj, 256>>>(x1, Wq1, q1,   nullptr, N1, INNER, D, xs, qs,  0);
    sgemm64<<<gproj, 256>>>(x1, Wk1, kbuf, nullptr, N1, INNER, D, xs, kvs, 0);
    sgemm64<<<gproj, 256>>>(x1, Wv1, vbuf, nullptr, N1, INNER, D, xs, kvs, 0);
    sgemm64<<<gproj, 256>>>(x2, Wk2, kbuf, nullptr, N2, INNER, D, xs, kvs, off2);
    sgemm64<<<gproj, 256>>>(x2, Wv2, vbuf, nullptr, N2, INNER, D, xs, kvs, off2);

    // 2) Attention
    const int smem = (4 * 64 * PAD + 3 * 64) * (int)sizeof(float);  // ~70.4 KB
    cudaFuncSetAttribute(flash_attn, cudaFuncAttributeMaxDynamicSharedMemorySize, smem);
    dim3 gattn(N1 / 64, HEADS, B);           // (32, 8, 4)
    flash_attn<<<gattn, 256, smem>>>(q1, kbuf, vbuf, aobuf);

    // 3) Output projection + bias
    sgemm64<<<gout, 256>>>(aobuf, Wo, out, bo, N1, D, INNER, qs, (size_t)N1 * D, 0);
}

// round 4
// speedup vs baseline: 2.3776x; 2.3776x over previous
#include <cuda_runtime.h>
#include <cuda_bf16.h>
#include <cstddef>
#include <cstdint>

// ---------------------------------------------------------------------------
// Problem constants
// ---------------------------------------------------------------------------
#define B     4
#define N1    2048
#define N2    2048
#define D     1024
#define HEADS 8
#define DHEAD 64
#define INNER (HEADS * DHEAD)     // 512
#define NKV   (N1 + N2)           // 4096
#define MTOT  (B * N1)            // 8192

// Scratch (device globals — no allocation allowed)
__device__ float g_q1[(size_t)B * N1 * INNER];   // 16 MB
__device__ float g_k [(size_t)B * NKV * INNER];  // 32 MB
__device__ float g_v [(size_t)B * NKV * INNER];  // 32 MB
__device__ float g_ao[(size_t)B * N1 * INNER];   // 16 MB
#define WSZ (1024 * 512)
__device__ float g_wt[6 * WSZ];                  // transposed weights [N,K]

// ---------------------------------------------------------------------------
// tf32 helpers (baseline PTX only — no 'a'-target features)
// ---------------------------------------------------------------------------
__device__ __forceinline__ float tf32_rna(float x) {
    float r;
    asm("cvt.rna.tf32.f32 %0, %1;" : "=f"(r) : "f"(x));
    return r;
}

// mma.sync m16n8k8 tf32: D += A*B. A row-major (16x8), B col-major (8x8).
__device__ __forceinline__ void mma_tf32(float* d, const uint32_t* a, const uint32_t* b) {
    asm volatile(
        "mma.sync.aligned.m16n8k8.row.col.f32.tf32.tf32.f32 "
        "{%0,%1,%2,%3}, {%4,%5,%6,%7}, {%8,%9}, {%0,%1,%2,%3};"
        : "+f"(d[0]), "+f"(d[1]), "+f"(d[2]), "+f"(d[3])
        : "r"(a[0]), "r"(a[1]), "r"(a[2]), "r"(a[3]), "r"(b[0]), "r"(b[1]));
}

// ---------------------------------------------------------------------------
// Weight transpose: src[R,C] -> dst[C,R]
// ---------------------------------------------------------------------------
__global__ void transpose_w(const float* __restrict__ src, float* __restrict__ dst,
                            int R, int C)
{
    __shared__ float t[32][33];
    int bx = blockIdx.x * 32, by = blockIdx.y * 32;
    int x = bx + threadIdx.x;
    for (int i = threadIdx.y; i < 32; i += 8)
        t[i][threadIdx.x] = src[(size_t)(by + i) * C + x];
    __syncthreads();
    int ox = by + threadIdx.x;
    for (int i = threadIdx.y; i < 32; i += 8)
        dst[(size_t)(bx + i) * R + ox] = t[threadIdx.x][i];
}

// ---------------------------------------------------------------------------
// tf32 mma GEMM: C[m,n] = A[m,:K] @ Bt[n,:K]^T (+bias)
// Block tile 128x128, 8 warps (2 along M x 4 along N), warp tile 64x32, BK=32.
// A flat [MTOT,K]; row m of C lands at C + (m>>11)*cstride + (m&2047)*N + coff.
// ---------------------------------------------------------------------------
#define KP 36   // smem k-pitch: (36 mod 32)=4 -> conflict-free fragment LDS

__global__ __launch_bounds__(256)
void gemm_mma(const float* __restrict__ A, const float* __restrict__ Bt,
              float* __restrict__ C, const float* __restrict__ bias,
              int K, int N, size_t cstride, size_t coff)
{
    __shared__ float As[128 * KP];
    __shared__ float Bs[128 * KP];

    const int tid = threadIdx.x;
    const int w = tid >> 5, lane = tid & 31;
    const int g = lane >> 2, tg = lane & 3;
    const int wm = (w & 1) * 64, wn = (w >> 1) * 32;
    const int m0 = blockIdx.y * 128, n0 = blockIdx.x * 128;

    const int lr = tid >> 1;            // 0..127
    const int lc = (tid & 1) * 16;      // 0 or 16

    const float* Arow = A  + (size_t)(m0 + lr) * K + lc;
    const float* Brow = Bt + (size_t)(n0 + lr) * K + lc;
    float* Asw = &As[lr * KP + lc];
    float* Bsw = &Bs[lr * KP + lc];

    float acc[4][4][4] = {};

    for (int k0 = 0; k0 < K; k0 += 32) {
        __syncthreads();
        #pragma unroll
        for (int c = 0; c < 4; c++) {
            float4 va = *(const float4*)(Arow + k0 + 4 * c);
            Asw[4*c + 0] = tf32_rna(va.x);
            Asw[4*c + 1] = tf32_rna(va.y);
            Asw[4*c + 2] = tf32_rna(va.z);
            Asw[4*c + 3] = tf32_rna(va.w);
            float4 vb = *(const float4*)(Brow + k0 + 4 * c);
            Bsw[4*c + 0] = tf32_rna(vb.x);
            Bsw[4*c + 1] = tf32_rna(vb.y);
            Bsw[4*c + 2] = tf32_rna(vb.z);
            Bsw[4*c + 3] = tf32_rna(vb.w);
        }
        __syncthreads();

        #pragma unroll
        for (int ks = 0; ks < 4; ks++) {
            uint32_t af[4][4], bf[4][2];
            #pragma unroll
            for (int mt = 0; mt < 4; mt++) {
                const float* p = &As[(wm + 16*mt + g) * KP + 8*ks + tg];
                af[mt][0] = __float_as_uint(p[0]);
                af[mt][1] = __float_as_uint(p[8 * KP]);
                af[mt][2] = __float_as_uint(p[4]);
                af[mt][3] = __float_as_uint(p[8 * KP + 4]);
            }
            #pragma unroll
            for (int nt = 0; nt < 4; nt++) {
                const float* p = &Bs[(wn + 8*nt + g) * KP + 8*ks + tg];
                bf[nt][0] = __float_as_uint(p[0]);
                bf[nt][1] = __float_as_uint(p[4]);
            }
            #pragma unroll
            for (int mt = 0; mt < 4; mt++)
                #pragma unroll
                for (int nt = 0; nt < 4; nt++)
                    mma_tf32(acc[mt][nt], af[mt], bf[nt]);
        }
    }

    // Epilogue: c0:[g][2tg] c1:[g][2tg+1] c2:[g+8][2tg] c3:[g+8][2tg+1]
    #pragma unroll
    for (int mt = 0; mt < 4; mt++) {
        const size_t r0 = (size_t)(m0 + wm + 16*mt + g);
        const size_t r1 = r0 + 8;
        float* c0 = C + (r0 >> 11) * cstride + (r0 & 2047) * N + coff;
        float* c1 = C + (r1 >> 11) * cstride + (r1 & 2047) * N + coff;
        #pragma unroll
        for (int nt = 0; nt < 4; nt++) {
            const int cc = n0 + wn + 8*nt + 2*tg;
            float bx = 0.f, by = 0.f;
            if (bias) { bx = bias[cc]; by = bias[cc + 1]; }
            *(float2*)&c0[cc] = make_float2(acc[mt][nt][0] + bx, acc[mt][nt][1] + by);
            *(float2*)&c1[cc] = make_float2(acc[mt][nt][2] + bx, acc[mt][nt][3] + by);
        }
    }
}

// ---------------------------------------------------------------------------
// Flash attention with tf32 mma.
// Block: 256 thr (8 warps), q-tile 128 rows, kv-tile 64. Warp w owns q rows
// [16w,16w+16). Smem pitch AP=68 -> conflict-free fragment LDS.
// ---------------------------------------------------------------------------
#define AP 68

__global__ __launch_bounds__(256)
void flash_mma(const float* __restrict__ q,
               const float* __restrict__ kc,
               const float* __restrict__ vc,
               float* __restrict__ ao)
{
    extern __shared__ float sm[];
    float* Qs   = sm;                  // 128*AP
    float* Ps   = Qs + 128 * AP;       // 128*AP (S, then P)
    float* Ks   = Ps + 128 * AP;       // 64*AP
    float* Vs   = Ks + 64 * AP;        // 64*AP
    float* mrow = Vs + 64 * AP;        // 128
    float* lrow = mrow + 128;          // 128
    float* arow = lrow + 128;          // 128
    float* pm   = arow + 128;          // 2*128
    float* psum = pm + 256;            // 2*128

    const int b  = blockIdx.z;
    const int h  = blockIdx.y;
    const int qt = blockIdx.x;
    const int tid = threadIdx.x;
    const int w = tid >> 5, lane = tid & 31;
    const int g = lane >> 2, tg = lane & 3;
    const int m0 = 16 * w;

    const float* qb = q  + ((size_t)b * N1 + (size_t)qt * 128) * INNER + h * DHEAD;
    const float* kb = kc + (size_t)b * NKV * INNER + h * DHEAD;
    const float* vb = vc + (size_t)b * NKV * INNER + h * DHEAD;

    // Load Q tile (pre-scaled, tf32-rounded): 128x64
    {
        const int r = tid >> 1, d0 = (tid & 1) * 32;
        const float* src = qb + (size_t)r * INNER + d0;
        float* dst = &Qs[r * AP + d0];
        #pragma unroll
        for (int c = 0; c < 8; c++) {
            float4 v = *(const float4*)(src + 4 * c);
            dst[4*c + 0] = tf32_rna(v.x * 0.125f);
            dst[4*c + 1] = tf32_rna(v.y * 0.125f);
            dst[4*c + 2] = tf32_rna(v.z * 0.125f);
            dst[4*c + 3] = tf32_rna(v.w * 0.125f);
        }
    }
    if (tid < 128) { mrow[tid] = -1e30f; lrow[tid] = 0.f; }

    float accO[8][4] = {};   // O fragments: [ntile][c0..c3]

    for (int j0 = 0; j0 < NKV; j0 += 64) {
        __syncthreads();

        // Load K,V tiles 64x64 (tf32-rounded)
        {
            const int r = tid >> 2, d0 = (tid & 3) * 16;
            const float* ksrc = kb + (size_t)(j0 + r) * INNER + d0;
            const float* vsrc = vb + (size_t)(j0 + r) * INNER + d0;
            float* kd = &Ks[r * AP + d0];
            float* vd = &Vs[r * AP + d0];
            #pragma unroll
            for (int c = 0; c < 4; c++) {
                float4 kv = *(const float4*)(ksrc + 4 * c);
                kd[4*c + 0] = tf32_rna(kv.x);
                kd[4*c + 1] = tf32_rna(kv.y);
                kd[4*c + 2] = tf32_rna(kv.z);
                kd[4*c + 3] = tf32_rna(kv.w);
                float4 vv = *(const float4*)(vsrc + 4 * c);
                vd[4*c + 0] = tf32_rna(vv.x);
                vd[4*c + 1] = tf32_rna(vv.y);
                vd[4*c + 2] = tf32_rna(vv.z);
                vd[4*c + 3] = tf32_rna(vv.w);
            }
        }
        __syncthreads();

        // S = Q @ K^T  (warp: 16 x 64), write S rows to Ps
        {
            float sacc[8][4] = {};
            #pragma unroll
            for (int ks = 0; ks < 8; ks++) {
                uint32_t af[4];
                const float* pa = &Qs[(m0 + g) * AP + 8*ks + tg];
                af[0] = __float_as_uint(pa[0]);
                af[1] = __float_as_uint(pa[8 * AP]);
                af[2] = __float_as_uint(pa[4]);
                af[3] = __float_as_uint(pa[8 * AP + 4]);
                #pragma unroll
                for (int nt = 0; nt < 8; nt++) {
                    uint32_t bf[2];
                    const float* pb = &Ks[(8*nt + g) * AP + 8*ks + tg];
                    bf[0] = __float_as_uint(pb[0]);
                    bf[1] = __float_as_uint(pb[4]);
                    mma_tf32(sacc[nt], af, bf);
                }
            }
            #pragma unroll
            for (int nt = 0; nt < 8; nt++) {
                *(float2*)&Ps[(m0 + g    ) * AP + 8*nt + 2*tg] = make_float2(sacc[nt][0], sacc[nt][1]);
                *(float2*)&Ps[(m0 + g + 8) * AP + 8*nt + 2*tg] = make_float2(sacc[nt][2], sacc[nt][3]);
            }
        }
        __syncthreads();

        // Softmax pass 1: partial row max (each thread scans 32 of 64 cols)
        {
            const int i = tid & 127, qh = tid >> 7;
            const float* prow = &Ps[i * AP + 32 * qh];
            float mx = -1e30f;
            #pragma unroll
            for (int c = 0; c < 8; c++) {
                float4 v = *(const float4*)(prow + 4 * c);
                mx = fmaxf(mx, fmaxf(fmaxf(v.x, v.y), fmaxf(v.z, v.w)));
            }
            pm[qh * 128 + i] = mx;
        }
        __syncthreads();

        // Softmax pass 2: exp + writeback (tf32-rounded) + partial sum
        {
            const int i = tid & 127, qh = tid >> 7;
            const float mt = fmaxf(mrow[i], fmaxf(pm[i], pm[128 + i]));
            float* prow = &Ps[i * AP + 32 * qh];
            float s = 0.f;
            #pragma unroll
            for (int c = 0; c < 8; c++) {
                float4 v = *(const float4*)(prow + 4 * c);
                v.x = __expf(v.x - mt);
                v.y = __expf(v.y - mt);
                v.z = __expf(v.z - mt);
                v.w = __expf(v.w - mt);
                s += v.x + v.y + v.z + v.w;
                v.x = tf32_rna(v.x); v.y = tf32_rna(v.y);
                v.z = tf32_rna(v.z); v.w = tf32_rna(v.w);
                *(float4*)(prow + 4 * c) = v;
            }
            psum[qh * 128 + i] = s;
        }
        __syncthreads();

        // Update running m, l, alpha
        if (tid < 128) {
            const int i = tid;
            const float mo = mrow[i];
            const float mt = fmaxf(mo, fmaxf(pm[i], pm[128 + i]));
            const float alpha = __expf(mo - mt);
            lrow[i] = lrow[i] * alpha + psum[i] + psum[128 + i];
            mrow[i] = mt;
            arow[i] = alpha;
        }
        __syncthreads();

        // O = O*alpha + P @ V   (warp: 16 x 64)
        {
            const float a0 = arow[m0 + g];
            const float a1 = arow[m0 + g + 8];
            #pragma unroll
            for (int nt = 0; nt < 8; nt++) {
                accO[nt][0] *= a0; accO[nt][1] *= a0;
                accO[nt][2] *= a1; accO[nt][3] *= a1;
            }
            #pragma unroll
            for (int ks = 0; ks < 8; ks++) {
                uint32_t af[4];
                const float* pa = &Ps[(m0 + g) * AP + 8*ks + tg];
                af[0] = __float_as_uint(pa[0]);
                af[1] = __float_as_uint(pa[8 * AP]);
                af[2] = __float_as_uint(pa[4]);
                af[3] = __float_as_uint(pa[8 * AP + 4]);
                #pragma unroll
                for (int nt = 0; nt < 8; nt++) {
                    uint32_t bf[2];
                    const float* pb = &Vs[(8*ks + tg) * AP + 8*nt + g];
                    bf[0] = __float_as_uint(pb[0]);
                    bf[1] = __float_as_uint(pb[4 * AP]);   // k+4 row
                    mma_tf32(accO[nt], af, bf);
                }
            }
        }
    }

    // Normalize and write O
    {
        const float linv0 = 1.0f / lrow[m0 + g];
        const float linv1 = 1.0f / lrow[m0 + g + 8];
        const size_t r = (size_t)b * N1 + (size_t)qt * 128 + m0 + g;
        float* d0 = ao + r * INNER + h * DHEAD;
        float* d1 = d0 + 8 * INNER;
        #pragma unroll
        for (int nt = 0; nt < 8; nt++) {
            const int cc = 8*nt + 2*tg;
            *(float2*)&d0[cc] = make_float2(accO[nt][0] * linv0, accO[nt][1] * linv0);
            *(float2*)&d1[cc] = make_float2(accO[nt][2] * linv1, accO[nt][3] * linv1);
        }
    }
}

// ---------------------------------------------------------------------------
// Launch
// ---------------------------------------------------------------------------
extern "C" void kernel_launch(void* const* d_in, const int* in_sizes, int n_in,
                              void* d_out, int out_size)
{
    (void)in_sizes; (void)n_in; (void)out_size;

    const float* x1  = (const float*)d_in[0];
    const float* x2  = (const float*)d_in[1];
    const float* Wq1 = (const float*)d_in[2];
    const float* Wk1 = (const float*)d_in[3];
    const float* Wv1 = (const float*)d_in[4];
    const float* Wk2 = (const float*)d_in[5];
    const float* Wv2 = (const float*)d_in[6];
    const float* Wo  = (const float*)d_in[7];
    const float* bo  = (const float*)d_in[8];
    float* out = (float*)d_out;

    float *q1, *kbuf, *vbuf, *aobuf, *wt;
    cudaGetSymbolAddress((void**)&q1,    g_q1);
    cudaGetSymbolAddress((void**)&kbuf,  g_k);
    cudaGetSymbolAddress((void**)&vbuf,  g_v);
    cudaGetSymbolAddress((void**)&aobuf, g_ao);
    cudaGetSymbolAddress((void**)&wt,    g_wt);

    // 0) Transpose weights [K,N] -> [N,K]
    dim3 tb(32, 8);
    dim3 tg1(INNER / 32, D / 32);
    transpose_w<<<tg1, tb>>>(Wq1, wt + 0 * WSZ, D, INNER);
    transpose_w<<<tg1, tb>>>(Wk1, wt + 1 * WSZ, D, INNER);
    transpose_w<<<tg1, tb>>>(Wv1, wt + 2 * WSZ, D, INNER);
    transpose_w<<<tg1, tb>>>(Wk2, wt + 3 * WSZ, D, INNER);
    transpose_w<<<tg1, tb>>>(Wv2, wt + 4 * WSZ, D, INNER);
    dim3 tg2(D / 32, INNER / 32);
    transpose_w<<<tg2, tb>>>(Wo, wt + 5 * WSZ, INNER, D);

    const size_t kvs  = (size_t)NKV * INNER;
    const size_t off2 = (size_t)N1 * INNER;

    // 1) Projections (tf32 mma)
    dim3 gp(INNER / 128, MTOT / 128);          // (4, 64)
    gemm_mma<<<gp, 256>>>(x1, wt + 0 * WSZ, q1,   nullptr, D, INNER, (size_t)N1 * INNER, 0);
    gemm_mma<<<gp, 256>>>(x1, wt + 1 * WSZ, kbuf, nullptr, D, INNER, kvs, 0);
    gemm_mma<<<gp, 256>>>(x1, wt + 2 * WSZ, vbuf, nullptr, D, INNER, kvs, 0);
    gemm_mma<<<gp, 256>>>(x2, wt + 3 * WSZ, kbuf, nullptr, D, INNER, kvs, off2);
    gemm_mma<<<gp, 256>>>(x2, wt + 4 * WSZ, vbuf, nullptr, D, INNER, kvs, off2);

    // 2) Attention (tf32 mma flash)
    const int smem = (2 * 128 * AP + 2 * 64 * AP + 3 * 128 + 2 * 256) * (int)sizeof(float);
    cudaFuncSetAttribute(flash_mma, cudaFuncAttributeMaxDynamicSharedMemorySize, smem);
    dim3 gattn(N1 / 128, HEADS, B);            // (16, 8, 4)
    flash_mma<<<gattn, 256, smem>>>(q1, kbuf, vbuf, aobuf);

    // 3) Output projection + bias (tf32 mma)
    dim3 go(D / 128, MTOT / 128);              // (8, 64)
    gemm_mma<<<go, 256>>>(aobuf, wt + 5 * WSZ, out, bo, INNER, D, (size_t)N1 * D, 0);
}

// round 5
// speedup vs baseline: 2.9009x; 1.2201x over previous
#include <cuda_runtime.h>
#include <cuda_bf16.h>
#include <cstddef>
#include <cstdint>

// ---------------------------------------------------------------------------
// Problem constants
// ---------------------------------------------------------------------------
#define B     4
#define N1    2048
#define N2    2048
#define D     1024
#define HEADS 8
#define DHEAD 64
#define INNER (HEADS * DHEAD)     // 512
#define NKV   (N1 + N2)           // 4096
#define MTOT  (B * N1)            // 8192

#define SCALE_Q 0.18033688011112042f   // 0.125 * log2(e)

// Scratch (device globals — no allocation allowed)
__device__ float g_q1[(size_t)B * N1 * INNER];   // 16 MB (scaled+rounded)
__device__ float g_k [(size_t)B * NKV * INNER];  // 32 MB (rounded)
__device__ float g_v [(size_t)B * NKV * INNER];  // 32 MB (rounded)
__device__ float g_ao[(size_t)B * N1 * INNER];   // 16 MB (rounded)
#define WSZ (1024 * 512)
__device__ float g_wt[6 * WSZ];                  // transposed+rounded weights [N,K]
#define XF4 ((size_t)MTOT * D / 4)               // float4 count per x tensor
__device__ float g_xr[2 * (size_t)MTOT * D];     // rounded x1,x2 (64 MB)

// ---------------------------------------------------------------------------
// PTX helpers (baseline sm_80-level only — safe for compute_103 target)
// ---------------------------------------------------------------------------
__device__ __forceinline__ float tf32_rna(float x) {
    float r;
    asm("cvt.rna.tf32.f32 %0, %1;" : "=f"(r) : "f"(x));
    return r;
}
__device__ __forceinline__ uint32_t smem_u32(const void* p) {
    uint32_t a;
    asm("{ .reg .u64 t; cvta.to.shared.u64 t, %1; cvt.u32.u64 %0, t; }"
        : "=r"(a) : "l"(p));
    return a;
}
__device__ __forceinline__ void cpasync16(uint32_t dst, const void* src) {
    asm volatile("cp.async.cg.shared.global [%0], [%1], 16;"
                 :: "r"(dst), "l"(src) : "memory");
}
#define CP_COMMIT() asm volatile("cp.async.commit_group;" ::: "memory")
#define CP_WAIT0()  asm volatile("cp.async.wait_group 0;" ::: "memory")

// mma.sync m16n8k8 tf32: D += A*B. A row-major (16x8), B col-major (8x8).
__device__ __forceinline__ void mma_tf32(float* d, const uint32_t* a, const uint32_t* b) {
    asm volatile(
        "mma.sync.aligned.m16n8k8.row.col.f32.tf32.tf32.f32 "
        "{%0,%1,%2,%3}, {%4,%5,%6,%7}, {%8,%9}, {%0,%1,%2,%3};"
        : "+f"(d[0]), "+f"(d[1]), "+f"(d[2]), "+f"(d[3])
        : "r"(a[0]), "r"(a[1]), "r"(a[2]), "r"(a[3]), "r"(b[0]), "r"(b[1]));
}

// ---------------------------------------------------------------------------
// Fused weight transpose + tf32 round: 6 weights -> g_wt (each [N,K])
// ---------------------------------------------------------------------------
__global__ void transpose6(const float* __restrict__ Wq1, const float* __restrict__ Wk1,
                           const float* __restrict__ Wv1, const float* __restrict__ Wk2,
                           const float* __restrict__ Wv2, const float* __restrict__ Wo,
                           float* __restrict__ wt)
{
    __shared__ float t[32][33];
    const int z = blockIdx.z;
    const float* src = (z == 0) ? Wq1 : (z == 1) ? Wk1 : (z == 2) ? Wv1
                     : (z == 3) ? Wk2 : (z == 4) ? Wv2 : Wo;
    const int R = (z < 5) ? D : INNER;
    const int C = (z < 5) ? INNER : D;
    float* dst = wt + (size_t)z * WSZ;

    const int bx = blockIdx.x * 32, by = blockIdx.y * 32;
    if (bx >= C || by >= R) return;
    const int x = bx + threadIdx.x;
    for (int i = threadIdx.y; i < 32; i += 8)
        t[i][threadIdx.x] = src[(size_t)(by + i) * C + x];
    __syncthreads();
    const int ox = by + threadIdx.x;
    for (int i = threadIdx.y; i < 32; i += 8)
        dst[(size_t)(bx + i) * R + ox] = tf32_rna(t[threadIdx.x][i]);
}

// ---------------------------------------------------------------------------
// Round x1, x2 to tf32 into g_xr
// ---------------------------------------------------------------------------
__global__ void round_x(const float* __restrict__ x1, const float* __restrict__ x2,
                        float* __restrict__ xr)
{
    const size_t total = 2 * XF4;
    for (size_t i = (size_t)blockIdx.x * blockDim.x + threadIdx.x;
         i < total; i += (size_t)gridDim.x * blockDim.x) {
        const float4 v = (i < XF4) ? ((const float4*)x1)[i] : ((const float4*)x2)[i - XF4];
        float4 o;
        o.x = tf32_rna(v.x); o.y = tf32_rna(v.y);
        o.z = tf32_rna(v.z); o.w = tf32_rna(v.w);
        ((float4*)xr)[i] = o;
    }
}

// ---------------------------------------------------------------------------
// cp.async double-buffered tf32 GEMM core.
// C[m,n] = A[m,:K] @ Bt[n,:K]^T, tile 128x128, BK=32, 8 warps, pitch KP=36.
// Inputs must already be tf32-rounded. Output: (acc*scale [+bias]) [rna].
// ---------------------------------------------------------------------------
#define KP 36
#define GBUF (128 * KP)             // floats per matrix buffer

__device__ __forceinline__ void gemm_core(
    const float* __restrict__ A, const float* __restrict__ Bt,
    float* __restrict__ C, const float* __restrict__ bias,
    int K, int N, size_t cstride, size_t coff, float scale, bool roundOut)
{
    extern __shared__ float gsm[];   // [2][A:GBUF | B:GBUF]

    const int tid = threadIdx.x;
    const int w = tid >> 5, lane = tid & 31;
    const int g = lane >> 2, tg = lane & 3;
    const int wm = (w & 1) * 64, wn = (w >> 1) * 32;
    const int m0 = blockIdx.y * 128, n0 = blockIdx.x * 128;

    const int lr = tid >> 1;            // 0..127
    const int lc = (tid & 1) * 16;      // 0 or 16

    const float* Ag = A  + (size_t)(m0 + lr) * K + lc;
    const float* Bg = Bt + (size_t)(n0 + lr) * K + lc;

    const uint32_t smb  = smem_u32(gsm);
    const uint32_t dstA = smb + (uint32_t)(lr * KP + lc) * 4;
    const uint32_t dstB = dstA + GBUF * 4;
    const uint32_t BUFB = 2 * GBUF * 4;

    // preload k-tile 0
    #pragma unroll
    for (int c = 0; c < 4; c++) {
        cpasync16(dstA + 16 * c, Ag + 4 * c);
        cpasync16(dstB + 16 * c, Bg + 4 * c);
    }
    CP_COMMIT();

    float acc[4][4][4] = {};
    const int S = K >> 5;
    for (int s = 0; s < S; s++) {
        CP_WAIT0();
        __syncthreads();
        if (s + 1 < S) {
            const uint32_t off = (uint32_t)((s + 1) & 1) * BUFB;
            const float* Ag2 = Ag + (s + 1) * 32;
            const float* Bg2 = Bg + (s + 1) * 32;
            #pragma unroll
            for (int c = 0; c < 4; c++) {
                cpasync16(dstA + off + 16 * c, Ag2 + 4 * c);
                cpasync16(dstB + off + 16 * c, Bg2 + 4 * c);
            }
            CP_COMMIT();
        }
        const float* As = gsm + (s & 1) * (2 * GBUF);
        const float* Bs = As + GBUF;

        #pragma unroll
        for (int ks = 0; ks < 4; ks++) {
            uint32_t af[4][4], bf[4][2];
            #pragma unroll
            for (int mt = 0; mt < 4; mt++) {
                const float* p = &As[(wm + 16 * mt + g) * KP + 8 * ks + tg];
                af[mt][0] = __float_as_uint(p[0]);
                af[mt][1] = __float_as_uint(p[8 * KP]);
                af[mt][2] = __float_as_uint(p[4]);
                af[mt][3] = __float_as_uint(p[8 * KP + 4]);
            }
            #pragma unroll
            for (int nt = 0; nt < 4; nt++) {
                const float* p = &Bs[(wn + 8 * nt + g) * KP + 8 * ks + tg];
                bf[nt][0] = __float_as_uint(p[0]);
                bf[nt][1] = __float_as_uint(p[4]);
            }
            #pragma unroll
            for (int mt = 0; mt < 4; mt++)
                #pragma unroll
                for (int nt = 0; nt < 4; nt++)
                    mma_tf32(acc[mt][nt], af[mt], bf[nt]);
        }
    }

    // Epilogue
    #pragma unroll
    for (int mt = 0; mt < 4; mt++) {
        const size_t r0 = (size_t)(m0 + wm + 16 * mt + g);
        const size_t r1 = r0 + 8;
        float* c0 = C + (r0 >> 11) * cstride + (r0 & 2047) * N + coff;
        float* c1 = C + (r1 >> 11) * cstride + (r1 & 2047) * N + coff;
        #pragma unroll
        for (int nt = 0; nt < 4; nt++) {
            const int cc = n0 + wn + 8 * nt + 2 * tg;
            float bx = 0.f, by = 0.f;
            if (bias) { bx = bias[cc]; by = bias[cc + 1]; }
            float v00 = acc[mt][nt][0] * scale + bx;
            float v01 = acc[mt][nt][1] * scale + by;
            float v10 = acc[mt][nt][2] * scale + bx;
            float v11 = acc[mt][nt][3] * scale + by;
            if (roundOut) {
                v00 = tf32_rna(v00); v01 = tf32_rna(v01);
                v10 = tf32_rna(v10); v11 = tf32_rna(v11);
            }
            *(float2*)&c0[cc] = make_float2(v00, v01);
            *(float2*)&c1[cc] = make_float2(v10, v11);
        }
    }
}

// Fused 5-projection launch: blockIdx.z selects {q1,k1,v1,k2,v2}
__global__ __launch_bounds__(256)
void gemm5(const float* __restrict__ x1r, const float* __restrict__ x2r,
           const float* __restrict__ wt,
           float* __restrict__ q1, float* __restrict__ k, float* __restrict__ v)
{
    const int z = blockIdx.z;
    const float* A = (z < 3) ? x1r : x2r;
    const float* W = wt + (size_t)z * WSZ;
    const size_t kvs  = (size_t)NKV * INNER;
    const size_t off2 = (size_t)N1 * INNER;
    float* Cp; size_t cs, co; float sc;
    if (z == 0)      { Cp = q1; cs = (size_t)N1 * INNER; co = 0;    sc = SCALE_Q; }
    else if (z == 1) { Cp = k;  cs = kvs;                co = 0;    sc = 1.f; }
    else if (z == 2) { Cp = v;  cs = kvs;                co = 0;    sc = 1.f; }
    else if (z == 3) { Cp = k;  cs = kvs;                co = off2; sc = 1.f; }
    else             { Cp = v;  cs = kvs;                co = off2; sc = 1.f; }
    gemm_core(A, W, Cp, nullptr, D, INNER, cs, co, sc, true);
}

__global__ __launch_bounds__(256)
void gemmO(const float* __restrict__ ao, const float* __restrict__ wt5,
           float* __restrict__ out, const float* __restrict__ bo)
{
    gemm_core(ao, wt5, out, bo, INNER, D, (size_t)N1 * D, 0, 1.f, false);
}

// ---------------------------------------------------------------------------
// Flash attention, FA2-style register softmax, cp.async K/V double buffer.
// Block 256 thr (8 warps), q-tile 128 (warp w: rows 16w..16w+16), kv-tile 64.
// q pre-scaled by 0.125*log2e and tf32-rounded; k/v tf32-rounded.
// Smem: Qs[128*AP] | buf0: K[64*AP],V[64*AP] | buf1: K,V.   AP=68.
// ---------------------------------------------------------------------------
#define AP 68
#define QS_F   (128 * AP)          // 8704 floats
#define KV_F   (64 * AP)           // 4352 floats
#define FBUF_F (2 * KV_F)          // 8704 floats per buffer

__global__ __launch_bounds__(256)
void flash2(const float* __restrict__ q, const float* __restrict__ kc,
            const float* __restrict__ vc, float* __restrict__ ao)
{
    extern __shared__ float fsm[];

    const int b  = blockIdx.z;
    const int h  = blockIdx.y;
    const int qt = blockIdx.x;
    const int tid  = threadIdx.x;
    const int w = tid >> 5, lane = tid & 31;
    const int g = lane >> 2, tg = lane & 3;
    const int m0 = 16 * w;

    const float* qb = q  + ((size_t)b * N1 + (size_t)qt * 128) * INNER + h * DHEAD;
    const float* kb = kc + (size_t)b * NKV * INNER + h * DHEAD;
    const float* vb = vc + (size_t)b * NKV * INNER + h * DHEAD;

    const uint32_t smb = smem_u32(fsm);

    // --- preload: Q tile + KV tile 0 via cp.async, one group ---
    {
        const int r = tid >> 1, c0 = (tid & 1) * 32;              // Q: 128 rows x 64
        const uint32_t qdst = smb + (uint32_t)(r * AP + c0) * 4;
        const float* qsrc = qb + (size_t)r * INNER + c0;
        #pragma unroll
        for (int c = 0; c < 8; c++) cpasync16(qdst + 16 * c, qsrc + 4 * c);
    }
    {
        const int r = tid >> 2, c0 = (tid & 3) * 16;              // K/V: 64 rows x 64
        const uint32_t kdst = smb + (uint32_t)(QS_F + r * AP + c0) * 4;
        const uint32_t vdst = kdst + KV_F * 4;
        const float* ks = kb + (size_t)r * INNER + c0;
        const float* vs = vb + (size_t)r * INNER + c0;
        #pragma unroll
        for (int c = 0; c < 4; c++) {
            cpasync16(kdst + 16 * c, ks + 4 * c);
            cpasync16(vdst + 16 * c, vs + 4 * c);
        }
    }
    CP_COMMIT();

    float accO[8][4] = {};
    float mrun0 = -1e30f, mrun1 = -1e30f, lrun0 = 0.f, lrun1 = 0.f;

    const int srcL = (lane & ~3) | (tg >> 1);
    const int srcH = srcL + 2;
    const bool hi = (tg & 1);

    const int NT = NKV / 64;   // 64 tiles
    for (int j = 0; j < NT; j++) {
        CP_WAIT0();
        __syncthreads();

        // prefetch tile j+1 into other buffer
        if (j + 1 < NT) {
            const int r = tid >> 2, c0 = (tid & 3) * 16;
            const uint32_t base = smb + (uint32_t)(QS_F + ((j + 1) & 1) * FBUF_F) * 4;
            const uint32_t kdst = base + (uint32_t)(r * AP + c0) * 4;
            const uint32_t vdst = kdst + KV_F * 4;
            const float* ks = kb + (size_t)(j + 1) * 64 * INNER + (size_t)r * INNER + c0;
            const float* vs = vb + (size_t)(j + 1) * 64 * INNER + (size_t)r * INNER + c0;
            #pragma unroll
            for (int c = 0; c < 4; c++) {
                cpasync16(kdst + 16 * c, ks + 4 * c);
                cpasync16(vdst + 16 * c, vs + 4 * c);
            }
            CP_COMMIT();
        }

        const float* Ks = fsm + QS_F + (j & 1) * FBUF_F;
        const float* Vs = Ks + KV_F;
        const float* Qs = fsm;

        // --- S = Q @ K^T (warp: 16x64) ---
        float sacc[8][4] = {};
        #pragma unroll
        for (int ks = 0; ks < 8; ks++) {
            uint32_t af[4];
            const float* pa = &Qs[(m0 + g) * AP + 8 * ks + tg];
            af[0] = __float_as_uint(pa[0]);
            af[1] = __float_as_uint(pa[8 * AP]);
            af[2] = __float_as_uint(pa[4]);
            af[3] = __float_as_uint(pa[8 * AP + 4]);
            #pragma unroll
            for (int nt = 0; nt < 8; nt++) {
                uint32_t bf[2];
                const float* pb = &Ks[(8 * nt + g) * AP + 8 * ks + tg];
                bf[0] = __float_as_uint(pb[0]);
                bf[1] = __float_as_uint(pb[4]);
                mma_tf32(sacc[nt], af, bf);
            }
        }

        // --- register online softmax (rows m0+g and m0+g+8) ---
        float rm0 = -1e30f, rm1 = -1e30f;
        #pragma unroll
        for (int nt = 0; nt < 8; nt++) {
            rm0 = fmaxf(rm0, fmaxf(sacc[nt][0], sacc[nt][1]));
            rm1 = fmaxf(rm1, fmaxf(sacc[nt][2], sacc[nt][3]));
        }
        #pragma unroll
        for (int off = 1; off <= 2; off <<= 1) {
            rm0 = fmaxf(rm0, __shfl_xor_sync(0xFFFFFFFFu, rm0, off));
            rm1 = fmaxf(rm1, __shfl_xor_sync(0xFFFFFFFFu, rm1, off));
        }
        const float mn0 = fmaxf(mrun0, rm0);
        const float mn1 = fmaxf(mrun1, rm1);
        const float al0 = exp2f(mrun0 - mn0);
        const float al1 = exp2f(mrun1 - mn1);

        float rs0 = 0.f, rs1 = 0.f;
        #pragma unroll
        for (int nt = 0; nt < 8; nt++) {
            float p0 = exp2f(sacc[nt][0] - mn0);
            float p1 = exp2f(sacc[nt][1] - mn0);
            float p2 = exp2f(sacc[nt][2] - mn1);
            float p3 = exp2f(sacc[nt][3] - mn1);
            rs0 += p0 + p1;
            rs1 += p2 + p3;
            sacc[nt][0] = tf32_rna(p0);
            sacc[nt][1] = tf32_rna(p1);
            sacc[nt][2] = tf32_rna(p2);
            sacc[nt][3] = tf32_rna(p3);
        }
        #pragma unroll
        for (int off = 1; off <= 2; off <<= 1) {
            rs0 += __shfl_xor_sync(0xFFFFFFFFu, rs0, off);
            rs1 += __shfl_xor_sync(0xFFFFFFFFu, rs1, off);
        }
        lrun0 = lrun0 * al0 + rs0;
        lrun1 = lrun1 * al1 + rs1;
        mrun0 = mn0;
        mrun1 = mn1;

        // rescale O
        #pragma unroll
        for (int nt = 0; nt < 8; nt++) {
            accO[nt][0] *= al0; accO[nt][1] *= al0;
            accO[nt][2] *= al1; accO[nt][3] *= al1;
        }

        // --- O += P @ V  (P converted C-layout -> A-layout via shuffles) ---
        #pragma unroll
        for (int ks = 0; ks < 8; ks++) {
            const float v0 = __shfl_sync(0xFFFFFFFFu, sacc[ks][0], srcL);
            const float v1 = __shfl_sync(0xFFFFFFFFu, sacc[ks][1], srcL);
            const float v2 = __shfl_sync(0xFFFFFFFFu, sacc[ks][2], srcL);
            const float v3 = __shfl_sync(0xFFFFFFFFu, sacc[ks][3], srcL);
            const float w0 = __shfl_sync(0xFFFFFFFFu, sacc[ks][0], srcH);
            const float w1 = __shfl_sync(0xFFFFFFFFu, sacc[ks][1], srcH);
            const float w2 = __shfl_sync(0xFFFFFFFFu, sacc[ks][2], srcH);
            const float w3 = __shfl_sync(0xFFFFFFFFu, sacc[ks][3], srcH);
            uint32_t af[4];
            af[0] = __float_as_uint(hi ? v1 : v0);   // P[g   ][8ks+tg  ]
            af[1] = __float_as_uint(hi ? v3 : v2);   // P[g+8 ][8ks+tg  ]
            af[2] = __float_as_uint(hi ? w1 : w0);   // P[g   ][8ks+tg+4]
            af[3] = __float_as_uint(hi ? w3 : w2);   // P[g+8 ][8ks+tg+4]
            #pragma unroll
            for (int nt = 0; nt < 8; nt++) {
                uint32_t bf[2];
                const float* pb = &Vs[(8 * ks + tg) * AP + 8 * nt + g];
                bf[0] = __float_as_uint(pb[0]);
                bf[1] = __float_as_uint(pb[4 * AP]);
                mma_tf32(accO[nt], af, bf);
            }
        }
    }

    // --- normalize + write (tf32-rounded for the final gemm) ---
    {
        const float li0 = 1.0f / lrun0;
        const float li1 = 1.0f / lrun1;
        const size_t r = (size_t)b * N1 + (size_t)qt * 128 + m0 + g;
        float* d0 = ao + r * INNER + h * DHEAD;
        float* d1 = d0 + 8 * INNER;
        #pragma unroll
        for (int nt = 0; nt < 8; nt++) {
            const int cc = 8 * nt + 2 * tg;
            *(float2*)&d0[cc] = make_float2(tf32_rna(accO[nt][0] * li0),
                                            tf32_rna(accO[nt][1] * li0));
            *(float2*)&d1[cc] = make_float2(tf32_rna(accO[nt][2] * li1),
                                            tf32_rna(accO[nt][3] * li1));
        }
    }
}

// ---------------------------------------------------------------------------
// Launch
// ---------------------------------------------------------------------------
extern "C" void kernel_launch(void* const* d_in, const int* in_sizes, int n_in,
                              void* d_out, int out_size)
{
    (void)in_sizes; (void)n_in; (void)out_size;

    const float* x1  = (const float*)d_in[0];
    const float* x2  = (const float*)d_in[1];
    const float* Wq1 = (const float*)d_in[2];
    const float* Wk1 = (const float*)d_in[3];
    const float* Wv1 = (const float*)d_in[4];
    const float* Wk2 = (const float*)d_in[5];
    const float* Wv2 = (const float*)d_in[6];
    const float* Wo  = (const float*)d_in[7];
    const float* bo  = (const float*)d_in[8];
    float* out = (float*)d_out;

    float *q1, *kbuf, *vbuf, *aobuf, *wt, *xr;
    cudaGetSymbolAddress((void**)&q1,    g_q1);
    cudaGetSymbolAddress((void**)&kbuf,  g_k);
    cudaGetSymbolAddress((void**)&vbuf,  g_v);
    cudaGetSymbolAddress((void**)&aobuf, g_ao);
    cudaGetSymbolAddress((void**)&wt,    g_wt);
    cudaGetSymbolAddress((void**)&xr,    g_xr);

    const int gemm_smem  = 4 * GBUF * (int)sizeof(float);                 // 73728
    const int flash_smem = (QS_F + 2 * FBUF_F) * (int)sizeof(float);      // 104448
    cudaFuncSetAttribute(gemm5,  cudaFuncAttributeMaxDynamicSharedMemorySize, gemm_smem);
    cudaFuncSetAttribute(gemmO,  cudaFuncAttributeMaxDynamicSharedMemorySize, gemm_smem);
    cudaFuncSetAttribute(flash2, cudaFuncAttributeMaxDynamicSharedMemorySize, flash_smem);

    // 0) weight transpose (+tf32 round), x rounding
    transpose6<<<dim3(32, 32, 6), dim3(32, 8)>>>(Wq1, Wk1, Wv1, Wk2, Wv2, Wo, wt);
    round_x<<<4096, 256>>>(x1, x2, xr);

    // 1) fused projections (q1 scaled by 0.125*log2e; all outputs tf32-rounded)
    gemm5<<<dim3(INNER / 128, MTOT / 128, 5), 256, gemm_smem>>>(
        xr, xr + (size_t)MTOT * D, wt, q1, kbuf, vbuf);

    // 2) flash attention
    flash2<<<dim3(N1 / 128, HEADS, B), 256, flash_smem>>>(q1, kbuf, vbuf, aobuf);

    // 3) output projection + bias
    gemmO<<<dim3(D / 128, MTOT / 128, 1), 256, gemm_smem>>>(aobuf, wt + 5 * WSZ, out, bo);
}

// round 6
// speedup vs baseline: 2.9341x; 1.0114x over previous
#include <cuda_runtime.h>
#include <cuda_bf16.h>
#include <cstddef>
#include <cstdint>

// ---------------------------------------------------------------------------
// Problem constants
// ---------------------------------------------------------------------------
#define B     4
#define N1    2048
#define N2    2048
#define D     1024
#define HEADS 8
#define DHEAD 64
#define INNER (HEADS * DHEAD)     // 512
#define NKV   (N1 + N2)           // 4096
#define MTOT  (B * N1)            // 8192

#define SCALE_Q 0.18033688011112042f   // 0.125 * log2(e)

// Scratch (device globals — no allocation allowed)
__device__ float g_q1[(size_t)B * N1 * INNER];   // 16 MB (scaled+rounded)
__device__ float g_k [(size_t)B * NKV * INNER];  // 32 MB (rounded)
__device__ float g_v [(size_t)B * NKV * INNER];  // 32 MB (rounded)
__device__ float g_ao[(size_t)B * N1 * INNER];   // 16 MB (rounded)
#define WSZ (1024 * 512)
__device__ float g_wt[6 * WSZ];                  // transposed+rounded weights [N,K]
#define XF4 ((size_t)MTOT * D / 4)
__device__ float g_xr[2 * (size_t)MTOT * D];     // rounded x1,x2 (64 MB)

// ---------------------------------------------------------------------------
// PTX helpers (baseline sm_80-level only — safe for compute_103 target)
// ---------------------------------------------------------------------------
__device__ __forceinline__ float tf32_rna(float x) {
    float r;
    asm("cvt.rna.tf32.f32 %0, %1;" : "=f"(r) : "f"(x));
    return r;
}
__device__ __forceinline__ uint32_t smem_u32(const void* p) {
    uint32_t a;
    asm("{ .reg .u64 t; cvta.to.shared.u64 t, %1; cvt.u32.u64 %0, t; }"
        : "=r"(a) : "l"(p));
    return a;
}
__device__ __forceinline__ void cpasync16(uint32_t dst, const void* src) {
    asm volatile("cp.async.cg.shared.global [%0], [%1], 16;"
                 :: "r"(dst), "l"(src) : "memory");
}
#define CP_COMMIT() asm volatile("cp.async.commit_group;" ::: "memory")
#define CP_WAIT0()  asm volatile("cp.async.wait_group 0;" ::: "memory")

// mma.sync m16n8k8 tf32: D += A*B. A row-major (16x8), B col-major (8x8).
__device__ __forceinline__ void mma_tf32(float* d, const uint32_t* a, const uint32_t* b) {
    asm volatile(
        "mma.sync.aligned.m16n8k8.row.col.f32.tf32.tf32.f32 "
        "{%0,%1,%2,%3}, {%4,%5,%6,%7}, {%8,%9}, {%0,%1,%2,%3};"
        : "+f"(d[0]), "+f"(d[1]), "+f"(d[2]), "+f"(d[3])
        : "r"(a[0]), "r"(a[1]), "r"(a[2]), "r"(a[3]), "r"(b[0]), "r"(b[1]));
}

// ---------------------------------------------------------------------------
// Fused weight transpose + tf32 round: 6 weights -> g_wt (each [N,K])
// ---------------------------------------------------------------------------
__global__ void transpose6(const float* __restrict__ Wq1, const float* __restrict__ Wk1,
                           const float* __restrict__ Wv1, const float* __restrict__ Wk2,
                           const float* __restrict__ Wv2, const float* __restrict__ Wo,
                           float* __restrict__ wt)
{
    __shared__ float t[32][33];
    const int z = blockIdx.z;
    const float* src = (z == 0) ? Wq1 : (z == 1) ? Wk1 : (z == 2) ? Wv1
                     : (z == 3) ? Wk2 : (z == 4) ? Wv2 : Wo;
    const int R = (z < 5) ? D : INNER;
    const int C = (z < 5) ? INNER : D;
    float* dst = wt + (size_t)z * WSZ;

    const int bx = blockIdx.x * 32, by = blockIdx.y * 32;
    if (bx >= C || by >= R) return;
    const int x = bx + threadIdx.x;
    for (int i = threadIdx.y; i < 32; i += 8)
        t[i][threadIdx.x] = src[(size_t)(by + i) * C + x];
    __syncthreads();
    const int ox = by + threadIdx.x;
    for (int i = threadIdx.y; i < 32; i += 8)
        dst[(size_t)(bx + i) * R + ox] = tf32_rna(t[threadIdx.x][i]);
}

// ---------------------------------------------------------------------------
// Round x1, x2 to tf32 into g_xr
// ---------------------------------------------------------------------------
__global__ void round_x(const float* __restrict__ x1, const float* __restrict__ x2,
                        float* __restrict__ xr)
{
    const size_t total = 2 * XF4;
    for (size_t i = (size_t)blockIdx.x * blockDim.x + threadIdx.x;
         i < total; i += (size_t)gridDim.x * blockDim.x) {
        const float4 v = (i < XF4) ? ((const float4*)x1)[i] : ((const float4*)x2)[i - XF4];
        float4 o;
        o.x = tf32_rna(v.x); o.y = tf32_rna(v.y);
        o.z = tf32_rna(v.z); o.w = tf32_rna(v.w);
        ((float4*)xr)[i] = o;
    }
}

// ---------------------------------------------------------------------------
// cp.async double-buffered tf32 GEMM core (128x128, BK=32, 8 warps, KP=36)
// ---------------------------------------------------------------------------
#define KP 36
#define GBUF (128 * KP)

__device__ __forceinline__ void gemm_core(
    const float* __restrict__ A, const float* __restrict__ Bt,
    float* __restrict__ C, const float* __restrict__ bias,
    int K, int N, size_t cstride, size_t coff, float scale, bool roundOut)
{
    extern __shared__ float gsm[];

    const int tid = threadIdx.x;
    const int w = tid >> 5, lane = tid & 31;
    const int g = lane >> 2, tg = lane & 3;
    const int wm = (w & 1) * 64, wn = (w >> 1) * 32;
    const int m0 = blockIdx.y * 128, n0 = blockIdx.x * 128;

    const int lr = tid >> 1;
    const int lc = (tid & 1) * 16;

    const float* Ag = A  + (size_t)(m0 + lr) * K + lc;
    const float* Bg = Bt + (size_t)(n0 + lr) * K + lc;

    const uint32_t smb  = smem_u32(gsm);
    const uint32_t dstA = smb + (uint32_t)(lr * KP + lc) * 4;
    const uint32_t dstB = dstA + GBUF * 4;
    const uint32_t BUFB = 2 * GBUF * 4;

    #pragma unroll
    for (int c = 0; c < 4; c++) {
        cpasync16(dstA + 16 * c, Ag + 4 * c);
        cpasync16(dstB + 16 * c, Bg + 4 * c);
    }
    CP_COMMIT();

    float acc[4][4][4] = {};
    const int S = K >> 5;
    for (int s = 0; s < S; s++) {
        CP_WAIT0();
        __syncthreads();
        if (s + 1 < S) {
            const uint32_t off = (uint32_t)((s + 1) & 1) * BUFB;
            const float* Ag2 = Ag + (s + 1) * 32;
            const float* Bg2 = Bg + (s + 1) * 32;
            #pragma unroll
            for (int c = 0; c < 4; c++) {
                cpasync16(dstA + off + 16 * c, Ag2 + 4 * c);
                cpasync16(dstB + off + 16 * c, Bg2 + 4 * c);
            }
            CP_COMMIT();
        }
        const float* As = gsm + (s & 1) * (2 * GBUF);
        const float* Bs = As + GBUF;

        #pragma unroll
        for (int ks = 0; ks < 4; ks++) {
            uint32_t af[4][4], bf[4][2];
            #pragma unroll
            for (int mt = 0; mt < 4; mt++) {
                const float* p = &As[(wm + 16 * mt + g) * KP + 8 * ks + tg];
                af[mt][0] = __float_as_uint(p[0]);
                af[mt][1] = __float_as_uint(p[8 * KP]);
                af[mt][2] = __float_as_uint(p[4]);
                af[mt][3] = __float_as_uint(p[8 * KP + 4]);
            }
            #pragma unroll
            for (int nt = 0; nt < 4; nt++) {
                const float* p = &Bs[(wn + 8 * nt + g) * KP + 8 * ks + tg];
                bf[nt][0] = __float_as_uint(p[0]);
                bf[nt][1] = __float_as_uint(p[4]);
            }
            #pragma unroll
            for (int mt = 0; mt < 4; mt++)
                #pragma unroll
                for (int nt = 0; nt < 4; nt++)
                    mma_tf32(acc[mt][nt], af[mt], bf[nt]);
        }
    }

    #pragma unroll
    for (int mt = 0; mt < 4; mt++) {
        const size_t r0 = (size_t)(m0 + wm + 16 * mt + g);
        const size_t r1 = r0 + 8;
        float* c0 = C + (r0 >> 11) * cstride + (r0 & 2047) * N + coff;
        float* c1 = C + (r1 >> 11) * cstride + (r1 & 2047) * N + coff;
        #pragma unroll
        for (int nt = 0; nt < 4; nt++) {
            const int cc = n0 + wn + 8 * nt + 2 * tg;
            float bx = 0.f, by = 0.f;
            if (bias) { bx = bias[cc]; by = bias[cc + 1]; }
            float v00 = acc[mt][nt][0] * scale + bx;
            float v01 = acc[mt][nt][1] * scale + by;
            float v10 = acc[mt][nt][2] * scale + bx;
            float v11 = acc[mt][nt][3] * scale + by;
            if (roundOut) {
                v00 = tf32_rna(v00); v01 = tf32_rna(v01);
                v10 = tf32_rna(v10); v11 = tf32_rna(v11);
            }
            *(float2*)&c0[cc] = make_float2(v00, v01);
            *(float2*)&c1[cc] = make_float2(v10, v11);
        }
    }
}

__global__ __launch_bounds__(256, 2)
void gemm5(const float* __restrict__ x1r, const float* __restrict__ x2r,
           const float* __restrict__ wt,
           float* __restrict__ q1, float* __restrict__ k, float* __restrict__ v)
{
    const int z = blockIdx.z;
    const float* A = (z < 3) ? x1r : x2r;
    const float* W = wt + (size_t)z * WSZ;
    const size_t kvs  = (size_t)NKV * INNER;
    const size_t off2 = (size_t)N1 * INNER;
    float* Cp; size_t cs, co; float sc;
    if (z == 0)      { Cp = q1; cs = (size_t)N1 * INNER; co = 0;    sc = SCALE_Q; }
    else if (z == 1) { Cp = k;  cs = kvs;                co = 0;    sc = 1.f; }
    else if (z == 2) { Cp = v;  cs = kvs;                co = 0;    sc = 1.f; }
    else if (z == 3) { Cp = k;  cs = kvs;                co = off2; sc = 1.f; }
    else             { Cp = v;  cs = kvs;                co = off2; sc = 1.f; }
    gemm_core(A, W, Cp, nullptr, D, INNER, cs, co, sc, true);
}

__global__ __launch_bounds__(256, 2)
void gemmO(const float* __restrict__ ao, const float* __restrict__ wt5,
           float* __restrict__ out, const float* __restrict__ bo)
{
    gemm_core(ao, wt5, out, bo, INNER, D, (size_t)N1 * D, 0, 1.f, false);
}

// ---------------------------------------------------------------------------
// Flash attention v3: Q fragments in registers, K/V cp.async double buffer.
// Block 256 thr (8 warps), q-tile 128 (warp w: rows 16w..16w+16), kv-tile 64.
// Smem = 2 x (K 64xAP + V 64xAP) = 68 KB -> 2 CTAs/SM.
// ---------------------------------------------------------------------------
#define AP 68
#define KV_F   (64 * AP)           // 4352 floats
#define FBUF_F (2 * KV_F)          // 8704 floats per stage

__global__ __launch_bounds__(256, 2)
void flash3(const float* __restrict__ q, const float* __restrict__ kc,
            const float* __restrict__ vc, float* __restrict__ ao)
{
    extern __shared__ float fsm[];

    const int b  = blockIdx.z;
    const int h  = blockIdx.y;
    const int qt = blockIdx.x;
    const int tid  = threadIdx.x;
    const int w = tid >> 5, lane = tid & 31;
    const int g = lane >> 2, tg = lane & 3;
    const int m0 = 16 * w;

    const float* qb = q  + ((size_t)b * N1 + (size_t)qt * 128) * INNER + h * DHEAD;
    const float* kb = kc + (size_t)b * NKV * INNER + h * DHEAD;
    const float* vb = vc + (size_t)b * NKV * INNER + h * DHEAD;

    const uint32_t smb = smem_u32(fsm);

    // --- kick off KV tile 0 prefetch first ---
    {
        const int r = tid >> 2, c0 = (tid & 3) * 16;
        const uint32_t kdst = smb + (uint32_t)(r * AP + c0) * 4;
        const uint32_t vdst = kdst + KV_F * 4;
        const float* ks = kb + (size_t)r * INNER + c0;
        const float* vs = vb + (size_t)r * INNER + c0;
        #pragma unroll
        for (int c = 0; c < 4; c++) {
            cpasync16(kdst + 16 * c, ks + 4 * c);
            cpasync16(vdst + 16 * c, vs + 4 * c);
        }
    }
    CP_COMMIT();

    // --- Q A-fragments directly from gmem (one-time, 32 regs) ---
    uint32_t qaf[8][4];
    {
        const float* q0 = qb + (size_t)(m0 + g) * INNER;       // row m0+g
        const float* q1r = q0 + 8 * INNER;                     // row m0+g+8
        #pragma unroll
        for (int ks = 0; ks < 8; ks++) {
            qaf[ks][0] = __float_as_uint(q0 [8 * ks + tg]);
            qaf[ks][1] = __float_as_uint(q1r[8 * ks + tg]);
            qaf[ks][2] = __float_as_uint(q0 [8 * ks + tg + 4]);
            qaf[ks][3] = __float_as_uint(q1r[8 * ks + tg + 4]);
        }
    }

    float accO[8][4] = {};
    float mrun0 = -1e30f, mrun1 = -1e30f, lrun0 = 0.f, lrun1 = 0.f;

    const int srcL = (lane & ~3) | (tg >> 1);
    const int srcH = srcL + 2;
    const bool hi = (tg & 1);

    const int NT = NKV / 64;
    for (int j = 0; j < NT; j++) {
        CP_WAIT0();
        __syncthreads();

        if (j + 1 < NT) {
            const int r = tid >> 2, c0 = (tid & 3) * 16;
            const uint32_t base = smb + (uint32_t)(((j + 1) & 1) * FBUF_F) * 4;
            const uint32_t kdst = base + (uint32_t)(r * AP + c0) * 4;
            const uint32_t vdst = kdst + KV_F * 4;
            const float* ks = kb + (size_t)(j + 1) * 64 * INNER + (size_t)r * INNER + c0;
            const float* vs = vb + (size_t)(j + 1) * 64 * INNER + (size_t)r * INNER + c0;
            #pragma unroll
            for (int c = 0; c < 4; c++) {
                cpasync16(kdst + 16 * c, ks + 4 * c);
                cpasync16(vdst + 16 * c, vs + 4 * c);
            }
            CP_COMMIT();
        }

        const float* Ks = fsm + (j & 1) * FBUF_F;
        const float* Vs = Ks + KV_F;

        // --- S = Q @ K^T (warp: 16x64) ---
        float sacc[8][4] = {};
        #pragma unroll
        for (int ks = 0; ks < 8; ks++) {
            #pragma unroll
            for (int nt = 0; nt < 8; nt++) {
                uint32_t bf[2];
                const float* pb = &Ks[(8 * nt + g) * AP + 8 * ks + tg];
                bf[0] = __float_as_uint(pb[0]);
                bf[1] = __float_as_uint(pb[4]);
                mma_tf32(sacc[nt], qaf[ks], bf);
            }
        }

        // --- register online softmax ---
        float rm0 = -1e30f, rm1 = -1e30f;
        #pragma unroll
        for (int nt = 0; nt < 8; nt++) {
            rm0 = fmaxf(rm0, fmaxf(sacc[nt][0], sacc[nt][1]));
            rm1 = fmaxf(rm1, fmaxf(sacc[nt][2], sacc[nt][3]));
        }
        #pragma unroll
        for (int off = 1; off <= 2; off <<= 1) {
            rm0 = fmaxf(rm0, __shfl_xor_sync(0xFFFFFFFFu, rm0, off));
            rm1 = fmaxf(rm1, __shfl_xor_sync(0xFFFFFFFFu, rm1, off));
        }
        const float mn0 = fmaxf(mrun0, rm0);
        const float mn1 = fmaxf(mrun1, rm1);
        const float al0 = exp2f(mrun0 - mn0);
        const float al1 = exp2f(mrun1 - mn1);

        float rs0 = 0.f, rs1 = 0.f;
        #pragma unroll
        for (int nt = 0; nt < 8; nt++) {
            float p0 = exp2f(sacc[nt][0] - mn0);
            float p1 = exp2f(sacc[nt][1] - mn0);
            float p2 = exp2f(sacc[nt][2] - mn1);
            float p3 = exp2f(sacc[nt][3] - mn1);
            rs0 += p0 + p1;
            rs1 += p2 + p3;
            sacc[nt][0] = tf32_rna(p0);
            sacc[nt][1] = tf32_rna(p1);
            sacc[nt][2] = tf32_rna(p2);
            sacc[nt][3] = tf32_rna(p3);
        }
        #pragma unroll
        for (int off = 1; off <= 2; off <<= 1) {
            rs0 += __shfl_xor_sync(0xFFFFFFFFu, rs0, off);
            rs1 += __shfl_xor_sync(0xFFFFFFFFu, rs1, off);
        }
        lrun0 = lrun0 * al0 + rs0;
        lrun1 = lrun1 * al1 + rs1;
        mrun0 = mn0;
        mrun1 = mn1;

        #pragma unroll
        for (int nt = 0; nt < 8; nt++) {
            accO[nt][0] *= al0; accO[nt][1] *= al0;
            accO[nt][2] *= al1; accO[nt][3] *= al1;
        }

        // --- O += P @ V (fragment relayout via shuffles) ---
        #pragma unroll
        for (int ks = 0; ks < 8; ks++) {
            const float v0 = __shfl_sync(0xFFFFFFFFu, sacc[ks][0], srcL);
            const float v1 = __shfl_sync(0xFFFFFFFFu, sacc[ks][1], srcL);
            const float v2 = __shfl_sync(0xFFFFFFFFu, sacc[ks][2], srcL);
            const float v3 = __shfl_sync(0xFFFFFFFFu, sacc[ks][3], srcL);
            const float w0 = __shfl_sync(0xFFFFFFFFu, sacc[ks][0], srcH);
            const float w1 = __shfl_sync(0xFFFFFFFFu, sacc[ks][1], srcH);
            const float w2 = __shfl_sync(0xFFFFFFFFu, sacc[ks][2], srcH);
            const float w3 = __shfl_sync(0xFFFFFFFFu, sacc[ks][3], srcH);
            uint32_t af[4];
            af[0] = __float_as_uint(hi ? v1 : v0);
            af[1] = __float_as_uint(hi ? v3 : v2);
            af[2] = __float_as_uint(hi ? w1 : w0);
            af[3] = __float_as_uint(hi ? w3 : w2);
            #pragma unroll
            for (int nt = 0; nt < 8; nt++) {
                uint32_t bf[2];
                const float* pb = &Vs[(8 * ks + tg) * AP + 8 * nt + g];
                bf[0] = __float_as_uint(pb[0]);
                bf[1] = __float_as_uint(pb[4 * AP]);
                mma_tf32(accO[nt], af, bf);
            }
        }
    }

    // --- normalize + write (tf32-rounded for the final gemm) ---
    {
        const float li0 = 1.0f / lrun0;
        const float li1 = 1.0f / lrun1;
        const size_t r = (size_t)b * N1 + (size_t)qt * 128 + m0 + g;
        float* d0 = ao + r * INNER + h * DHEAD;
        float* d1 = d0 + 8 * INNER;
        #pragma unroll
        for (int nt = 0; nt < 8; nt++) {
            const int cc = 8 * nt + 2 * tg;
            *(float2*)&d0[cc] = make_float2(tf32_rna(accO[nt][0] * li0),
                                            tf32_rna(accO[nt][1] * li0));
            *(float2*)&d1[cc] = make_float2(tf32_rna(accO[nt][2] * li1),
                                            tf32_rna(accO[nt][3] * li1));
        }
    }
}

// ---------------------------------------------------------------------------
// Launch
// ---------------------------------------------------------------------------
extern "C" void kernel_launch(void* const* d_in, const int* in_sizes, int n_in,
                              void* d_out, int out_size)
{
    (void)in_sizes; (void)n_in; (void)out_size;

    const float* x1  = (const float*)d_in[0];
    const float* x2  = (const float*)d_in[1];
    const float* Wq1 = (const float*)d_in[2];
    const float* Wk1 = (const float*)d_in[3];
    const float* Wv1 = (const float*)d_in[4];
    const float* Wk2 = (const float*)d_in[5];
    const float* Wv2 = (const float*)d_in[6];
    const float* Wo  = (const float*)d_in[7];
    const float* bo  = (const float*)d_in[8];
    float* out = (float*)d_out;

    float *q1, *kbuf, *vbuf, *aobuf, *wt, *xr;
    cudaGetSymbolAddress((void**)&q1,    g_q1);
    cudaGetSymbolAddress((void**)&kbuf,  g_k);
    cudaGetSymbolAddress((void**)&vbuf,  g_v);
    cudaGetSymbolAddress((void**)&aobuf, g_ao);
    cudaGetSymbolAddress((void**)&wt,    g_wt);
    cudaGetSymbolAddress((void**)&xr,    g_xr);

    const int gemm_smem  = 4 * GBUF * (int)sizeof(float);            // 73728
    const int flash_smem = 2 * FBUF_F * (int)sizeof(float);          // 69632
    cudaFuncSetAttribute(gemm5,  cudaFuncAttributeMaxDynamicSharedMemorySize, gemm_smem);
    cudaFuncSetAttribute(gemmO,  cudaFuncAttributeMaxDynamicSharedMemorySize, gemm_smem);
    cudaFuncSetAttribute(flash3, cudaFuncAttributeMaxDynamicSharedMemorySize, flash_smem);

    transpose6<<<dim3(32, 32, 6), dim3(32, 8)>>>(Wq1, Wk1, Wv1, Wk2, Wv2, Wo, wt);
    round_x<<<4096, 256>>>(x1, x2, xr);

    gemm5<<<dim3(INNER / 128, MTOT / 128, 5), 256, gemm_smem>>>(
        xr, xr + (size_t)MTOT * D, wt, q1, kbuf, vbuf);

    flash3<<<dim3(N1 / 128, HEADS, B), 256, flash_smem>>>(q1, kbuf, vbuf, aobuf);

    gemmO<<<dim3(D / 128, MTOT / 128, 1), 256, gemm_smem>>>(aobuf, wt + 5 * WSZ, out, bo);
}

// round 8
// speedup vs baseline: 6.7645x; 2.3055x over previous
#include <cuda_runtime.h>
#include <cuda_fp16.h>
#include <cstddef>
#include <cstdint>

// ---------------------------------------------------------------------------
// Problem constants
// ---------------------------------------------------------------------------
#define B     4
#define N1    2048
#define N2    2048
#define D     1024
#define HEADS 8
#define DHEAD 64
#define INNER (HEADS * DHEAD)     // 512
#define NKV   (N1 + N2)           // 4096
#define MTOT  (B * N1)            // 8192

#define SCALE_Q 0.18033688011112042f   // 0.125 * log2(e)

// Scratch (device globals — no allocation allowed), all fp16
__device__ __half g_q1[(size_t)B * N1 * INNER];
__device__ __half g_k [(size_t)B * NKV * INNER];
__device__ __half g_v [(size_t)B * NKV * INNER];
__device__ __half g_ao[(size_t)B * N1 * INNER];
#define WSZ (1024 * 512)
__device__ __half g_wt[6 * WSZ];                  // transposed weights [N,K]
__device__ __half g_xr[2 * (size_t)MTOT * D];     // converted x1,x2

// ---------------------------------------------------------------------------
// PTX helpers (baseline sm_80-level only — safe for compute_103 target)
// ---------------------------------------------------------------------------
__device__ __forceinline__ uint32_t smem_u32(const void* p) {
    uint32_t a;
    asm("{ .reg .u64 t; cvta.to.shared.u64 t, %1; cvt.u32.u64 %0, t; }"
        : "=r"(a) : "l"(p));
    return a;
}
__device__ __forceinline__ void cpasync16(uint32_t dst, const void* src) {
    asm volatile("cp.async.cg.shared.global [%0], [%1], 16;"
                 :: "r"(dst), "l"(src) : "memory");
}
#define CP_COMMIT() asm volatile("cp.async.commit_group;" ::: "memory")
#define CP_WAIT0()  asm volatile("cp.async.wait_group 0;" ::: "memory")

// f16 mma m16n8k16, f32 accumulate. A row-major (16x16), B col-major (16x8).
__device__ __forceinline__ void mma_f16(float* d, const uint32_t* a, const uint32_t* b) {
    asm volatile(
        "mma.sync.aligned.m16n8k16.row.col.f32.f16.f16.f32 "
        "{%0,%1,%2,%3}, {%4,%5,%6,%7}, {%8,%9}, {%0,%1,%2,%3};"
        : "+f"(d[0]), "+f"(d[1]), "+f"(d[2]), "+f"(d[3])
        : "r"(a[0]), "r"(a[1]), "r"(a[2]), "r"(a[3]), "r"(b[0]), "r"(b[1]));
}

__device__ __forceinline__ void ldmatrix_x4_trans(
    uint32_t& r0, uint32_t& r1, uint32_t& r2, uint32_t& r3, uint32_t addr)
{
    asm volatile("ldmatrix.sync.aligned.m8n8.x4.trans.shared.b16 {%0,%1,%2,%3}, [%4];"
                 : "=r"(r0), "=r"(r1), "=r"(r2), "=r"(r3) : "r"(addr));
}

__device__ __forceinline__ uint32_t packh2(float x, float y) {
    __half2 h = __floats2half2_rn(x, y);
    return *reinterpret_cast<uint32_t*>(&h);
}
__device__ __forceinline__ uint32_t ldh2(const __half* p) {
    return *reinterpret_cast<const uint32_t*>(p);
}

// ---------------------------------------------------------------------------
// Fused weight transpose + f16 convert: 6 weights -> g_wt (each [N,K])
// ---------------------------------------------------------------------------
__global__ void transpose6(const float* __restrict__ Wq1, const float* __restrict__ Wk1,
                           const float* __restrict__ Wv1, const float* __restrict__ Wk2,
                           const float* __restrict__ Wv2, const float* __restrict__ Wo,
                           __half* __restrict__ wt)
{
    __shared__ float t[32][33];
    const int z = blockIdx.z;
    const float* src = (z == 0) ? Wq1 : (z == 1) ? Wk1 : (z == 2) ? Wv1
                     : (z == 3) ? Wk2 : (z == 4) ? Wv2 : Wo;
    const int R = (z < 5) ? D : INNER;
    const int C = (z < 5) ? INNER : D;
    __half* dst = wt + (size_t)z * WSZ;

    const int bx = blockIdx.x * 32, by = blockIdx.y * 32;
    if (bx >= C || by >= R) return;
    const int x = bx + threadIdx.x;
    for (int i = threadIdx.y; i < 32; i += 8)
        t[i][threadIdx.x] = src[(size_t)(by + i) * C + x];
    __syncthreads();
    const int ox = by + threadIdx.x;
    for (int i = threadIdx.y; i < 32; i += 8)
        dst[(size_t)(bx + i) * R + ox] = __float2half_rn(t[threadIdx.x][i]);
}

// ---------------------------------------------------------------------------
// Convert x1, x2 to f16 into g_xr
// ---------------------------------------------------------------------------
#define XF4 ((size_t)MTOT * D / 4)
__global__ void conv_x(const float* __restrict__ x1, const float* __restrict__ x2,
                       __half* __restrict__ xr)
{
    const size_t total = 2 * XF4;
    for (size_t i = (size_t)blockIdx.x * blockDim.x + threadIdx.x;
         i < total; i += (size_t)gridDim.x * blockDim.x) {
        const float4 v = (i < XF4) ? ((const float4*)x1)[i] : ((const float4*)x2)[i - XF4];
        uint2 o;
        o.x = packh2(v.x, v.y);
        o.y = packh2(v.z, v.w);
        ((uint2*)xr)[i] = o;
    }
}

// ---------------------------------------------------------------------------
// cp.async double-buffered f16 GEMM core (128x128, BK=32, 8 warps)
// A [m][K] f16, Bt [n][K] f16.  Smem pitch 40 halves (80B row shift).
// ---------------------------------------------------------------------------
#define KP 40
#define GBUF (128 * KP)                 // halves per matrix buffer

__device__ __forceinline__ void gemm_core(
    const __half* __restrict__ A, const __half* __restrict__ Bt,
    void* __restrict__ C, const float* __restrict__ bias,
    int K, int N, size_t cstride, size_t coff, float scale, bool outHalf)
{
    extern __shared__ __half gsm[];

    const int tid = threadIdx.x;
    const int w = tid >> 5, lane = tid & 31;
    const int g = lane >> 2, tg = lane & 3;
    const int wm = (w & 1) * 64, wn = (w >> 1) * 32;
    const int m0 = blockIdx.y * 128, n0 = blockIdx.x * 128;

    const int lr = tid >> 1;
    const int lc = (tid & 1) * 16;     // halves offset: 0 or 16

    const __half* Ag = A  + (size_t)(m0 + lr) * K + lc;
    const __half* Bg = Bt + (size_t)(n0 + lr) * K + lc;

    const uint32_t smb  = smem_u32(gsm);
    const uint32_t dstA = smb + (uint32_t)(lr * KP + lc) * 2;
    const uint32_t dstB = dstA + GBUF * 2;
    const uint32_t BUFB = 2 * GBUF * 2;

    #pragma unroll
    for (int c = 0; c < 2; c++) {
        cpasync16(dstA + 16 * c, Ag + 8 * c);
        cpasync16(dstB + 16 * c, Bg + 8 * c);
    }
    CP_COMMIT();

    float acc[4][4][4] = {};
    const int S = K >> 5;
    for (int s = 0; s < S; s++) {
        CP_WAIT0();
        __syncthreads();
        if (s + 1 < S) {
            const uint32_t off = (uint32_t)((s + 1) & 1) * BUFB;
            const __half* Ag2 = Ag + (s + 1) * 32;
            const __half* Bg2 = Bg + (s + 1) * 32;
            #pragma unroll
            for (int c = 0; c < 2; c++) {
                cpasync16(dstA + off + 16 * c, Ag2 + 8 * c);
                cpasync16(dstB + off + 16 * c, Bg2 + 8 * c);
            }
            CP_COMMIT();
        }
        const __half* As = gsm + (s & 1) * (2 * GBUF);
        const __half* Bs = As + GBUF;

        #pragma unroll
        for (int ks = 0; ks < 2; ks++) {          // two k16 slices
            const int k0 = 16 * ks;
            uint32_t af[4][4], bf[4][2];
            #pragma unroll
            for (int mt = 0; mt < 4; mt++) {
                const __half* p0 = &As[(wm + 16 * mt + g) * KP + k0 + 2 * tg];
                const __half* p1 = p0 + 8 * KP;
                af[mt][0] = ldh2(p0);
                af[mt][1] = ldh2(p1);
                af[mt][2] = ldh2(p0 + 8);
                af[mt][3] = ldh2(p1 + 8);
            }
            #pragma unroll
            for (int nt = 0; nt < 4; nt++) {
                const __half* p = &Bs[(wn + 8 * nt + g) * KP + k0 + 2 * tg];
                bf[nt][0] = ldh2(p);
                bf[nt][1] = ldh2(p + 8);
            }
            #pragma unroll
            for (int mt = 0; mt < 4; mt++)
                #pragma unroll
                for (int nt = 0; nt < 4; nt++)
                    mma_f16(acc[mt][nt], af[mt], bf[nt]);
        }
    }

    #pragma unroll
    for (int mt = 0; mt < 4; mt++) {
        const size_t r0 = (size_t)(m0 + wm + 16 * mt + g);
        const size_t r1 = r0 + 8;
        const size_t o0 = (r0 >> 11) * cstride + (r0 & 2047) * N + coff;
        const size_t o1 = (r1 >> 11) * cstride + (r1 & 2047) * N + coff;
        #pragma unroll
        for (int nt = 0; nt < 4; nt++) {
            const int cc = n0 + wn + 8 * nt + 2 * tg;
            float v00 = acc[mt][nt][0] * scale;
            float v01 = acc[mt][nt][1] * scale;
            float v10 = acc[mt][nt][2] * scale;
            float v11 = acc[mt][nt][3] * scale;
            if (outHalf) {
                *(uint32_t*)((__half*)C + o0 + cc) = packh2(v00, v01);
                *(uint32_t*)((__half*)C + o1 + cc) = packh2(v10, v11);
            } else {
                const float bx = bias ? bias[cc] : 0.f;
                const float by = bias ? bias[cc + 1] : 0.f;
                *(float2*)((float*)C + o0 + cc) = make_float2(v00 + bx, v01 + by);
                *(float2*)((float*)C + o1 + cc) = make_float2(v10 + bx, v11 + by);
            }
        }
    }
}

__global__ __launch_bounds__(256, 2)
void gemm5(const __half* __restrict__ x1r, const __half* __restrict__ x2r,
           const __half* __restrict__ wt,
           __half* __restrict__ q1, __half* __restrict__ k, __half* __restrict__ v)
{
    const int z = blockIdx.z;
    const __half* A = (z < 3) ? x1r : x2r;
    const __half* W = wt + (size_t)z * WSZ;
    const size_t kvs  = (size_t)NKV * INNER;
    const size_t off2 = (size_t)N1 * INNER;
    __half* Cp; size_t cs, co; float sc;
    if (z == 0)      { Cp = q1; cs = (size_t)N1 * INNER; co = 0;    sc = SCALE_Q; }
    else if (z == 1) { Cp = k;  cs = kvs;                co = 0;    sc = 1.f; }
    else if (z == 2) { Cp = v;  cs = kvs;                co = 0;    sc = 1.f; }
    else if (z == 3) { Cp = k;  cs = kvs;                co = off2; sc = 1.f; }
    else             { Cp = v;  cs = kvs;                co = off2; sc = 1.f; }
    gemm_core(A, W, Cp, nullptr, D, INNER, cs, co, sc, true);
}

__global__ __launch_bounds__(256, 2)
void gemmO(const __half* __restrict__ ao, const __half* __restrict__ wt5,
           float* __restrict__ out, const float* __restrict__ bo)
{
    gemm_core(ao, wt5, out, bo, INNER, D, (size_t)N1 * D, 0, 1.f, false);
}

// ---------------------------------------------------------------------------
// Flash attention v4: all-f16 MMA path.
// Block 256 thr (8 warps), q-tile 128 (warp w: rows 16w..16w+16), kv-tile 64.
// K,V f16 in smem pitch 72 halves, double-buffered (36 KB total).
// S: Q(reg frags) @ K^T.  P: packed f16x2 straight from S accum (no shuffles).
// V B-frags via ldmatrix.x4.trans.
// ---------------------------------------------------------------------------
#define APH 72
#define KV_H   (64 * APH)           // halves per K (or V) tile
#define FBUF_H (2 * KV_H)           // halves per stage (K+V)

__global__ __launch_bounds__(256, 2)
void flash4(const __half* __restrict__ q, const __half* __restrict__ kc,
            const __half* __restrict__ vc, __half* __restrict__ ao)
{
    extern __shared__ __half fsm[];

    const int b  = blockIdx.z;
    const int h  = blockIdx.y;
    const int qt = blockIdx.x;
    const int tid  = threadIdx.x;
    const int w = tid >> 5, lane = tid & 31;
    const int g = lane >> 2, tg = lane & 3;
    const int m0 = 16 * w;

    const __half* qb = q  + ((size_t)b * N1 + (size_t)qt * 128) * INNER + h * DHEAD;
    const __half* kb = kc + (size_t)b * NKV * INNER + h * DHEAD;
    const __half* vb = vc + (size_t)b * NKV * INNER + h * DHEAD;

    const uint32_t smb = smem_u32(fsm);

    const int cr = tid >> 2;
    const int cc0 = (tid & 3) * 16;

    // --- kick off KV tile 0 prefetch ---
    {
        const uint32_t kdst = smb + (uint32_t)(cr * APH + cc0) * 2;
        const uint32_t vdst = kdst + KV_H * 2;
        const __half* ks = kb + (size_t)cr * INNER + cc0;
        const __half* vs = vb + (size_t)cr * INNER + cc0;
        #pragma unroll
        for (int c = 0; c < 2; c++) {
            cpasync16(kdst + 16 * c, ks + 8 * c);
            cpasync16(vdst + 16 * c, vs + 8 * c);
        }
    }
    CP_COMMIT();

    // --- Q A-fragments from gmem (16 regs: 4 k-slices x 4) ---
    uint32_t qaf[4][4];
    {
        const __half* q0 = qb + (size_t)(m0 + g) * INNER;
        const __half* q1r = q0 + 8 * INNER;
        #pragma unroll
        for (int s = 0; s < 4; s++) {
            qaf[s][0] = ldh2(q0  + 16 * s + 2 * tg);
            qaf[s][1] = ldh2(q1r + 16 * s + 2 * tg);
            qaf[s][2] = ldh2(q0  + 16 * s + 2 * tg + 8);
            qaf[s][3] = ldh2(q1r + 16 * s + 2 * tg + 8);
        }
    }

    float accO[8][4] = {};
    float mrun0 = -1e30f, mrun1 = -1e30f, lrun0 = 0.f, lrun1 = 0.f;

    // ldmatrix V addressing (per kv-slice ks, d-pair dp)
    const int vmat = lane >> 3;          // 0..3
    const int vrow = lane & 7;
    const int vr = (vmat & 1) * 8 + vrow;     // row within 16-kv slice
    const int vcb = (vmat >> 1) * 8;          // col offset within 16-d pair

    const int NT = NKV / 64;
    for (int j = 0; j < NT; j++) {
        CP_WAIT0();
        __syncthreads();

        if (j + 1 < NT) {
            const uint32_t base = smb + (uint32_t)(((j + 1) & 1) * FBUF_H) * 2;
            const uint32_t kdst = base + (uint32_t)(cr * APH + cc0) * 2;
            const uint32_t vdst = kdst + KV_H * 2;
            const __half* ks = kb + (size_t)(j + 1) * 64 * INNER + (size_t)cr * INNER + cc0;
            const __half* vs = vb + (size_t)(j + 1) * 64 * INNER + (size_t)cr * INNER + cc0;
            #pragma unroll
            for (int c = 0; c < 2; c++) {
                cpasync16(kdst + 16 * c, ks + 8 * c);
                cpasync16(vdst + 16 * c, vs + 8 * c);
            }
            CP_COMMIT();
        }

        const __half* Ks = fsm + (j & 1) * FBUF_H;
        const uint32_t vsb = smb + (uint32_t)((j & 1) * FBUF_H + KV_H) * 2;

        // --- S = Q @ K^T (warp: 16x64), 32 f16 MMAs ---
        float sacc[8][4] = {};
        #pragma unroll
        for (int ks = 0; ks < 4; ks++) {
            const int k0 = 16 * ks;
            #pragma unroll
            for (int nt = 0; nt < 8; nt++) {
                uint32_t bf[2];
                const __half* pb = &Ks[(8 * nt + g) * APH + k0 + 2 * tg];
                bf[0] = ldh2(pb);
                bf[1] = ldh2(pb + 8);
                mma_f16(sacc[nt], qaf[ks], bf);
            }
        }

        // --- register online softmax ---
        float rm0 = -1e30f, rm1 = -1e30f;
        #pragma unroll
        for (int nt = 0; nt < 8; nt++) {
            rm0 = fmaxf(rm0, fmaxf(sacc[nt][0], sacc[nt][1]));
            rm1 = fmaxf(rm1, fmaxf(sacc[nt][2], sacc[nt][3]));
        }
        #pragma unroll
        for (int off = 1; off <= 2; off <<= 1) {
            rm0 = fmaxf(rm0, __shfl_xor_sync(0xFFFFFFFFu, rm0, off));
            rm1 = fmaxf(rm1, __shfl_xor_sync(0xFFFFFFFFu, rm1, off));
        }
        const float mn0 = fmaxf(mrun0, rm0);
        const float mn1 = fmaxf(mrun1, rm1);
        const float al0 = exp2f(mrun0 - mn0);
        const float al1 = exp2f(mrun1 - mn1);

        float rs0 = 0.f, rs1 = 0.f;
        uint32_t paf[4][4];                  // P A-frags, packed while exping
        #pragma unroll
        for (int ks = 0; ks < 4; ks++) {
            const int e0 = 2 * ks, e1 = 2 * ks + 1;
            float p00 = exp2f(sacc[e0][0] - mn0);
            float p01 = exp2f(sacc[e0][1] - mn0);
            float p10 = exp2f(sacc[e0][2] - mn1);
            float p11 = exp2f(sacc[e0][3] - mn1);
            float p20 = exp2f(sacc[e1][0] - mn0);
            float p21 = exp2f(sacc[e1][1] - mn0);
            float p30 = exp2f(sacc[e1][2] - mn1);
            float p31 = exp2f(sacc[e1][3] - mn1);
            rs0 += p00 + p01 + p20 + p21;
            rs1 += p10 + p11 + p30 + p31;
            paf[ks][0] = packh2(p00, p01);
            paf[ks][1] = packh2(p10, p11);
            paf[ks][2] = packh2(p20, p21);
            paf[ks][3] = packh2(p30, p31);
        }
        #pragma unroll
        for (int off = 1; off <= 2; off <<= 1) {
            rs0 += __shfl_xor_sync(0xFFFFFFFFu, rs0, off);
            rs1 += __shfl_xor_sync(0xFFFFFFFFu, rs1, off);
        }
        lrun0 = lrun0 * al0 + rs0;
        lrun1 = lrun1 * al1 + rs1;
        mrun0 = mn0;
        mrun1 = mn1;

        #pragma unroll
        for (int nt = 0; nt < 8; nt++) {
            accO[nt][0] *= al0; accO[nt][1] *= al0;
            accO[nt][2] *= al1; accO[nt][3] *= al1;
        }

        // --- O += P @ V : ldmatrix.x4.trans B-frags, 32 f16 MMAs ---
        #pragma unroll
        for (int ks = 0; ks < 4; ks++) {
            #pragma unroll
            for (int dp = 0; dp < 4; dp++) {
                uint32_t r0, r1, r2, r3;
                const uint32_t addr = vsb +
                    (uint32_t)((16 * ks + vr) * APH + 16 * dp + vcb) * 2;
                ldmatrix_x4_trans(r0, r1, r2, r3, addr);
                uint32_t bf0[2] = { r0, r1 };
                uint32_t bf1[2] = { r2, r3 };
                mma_f16(accO[2 * dp],     paf[ks], bf0);
                mma_f16(accO[2 * dp + 1], paf[ks], bf1);
            }
        }
    }

    // --- normalize + write f16 ---
    {
        const float li0 = 1.0f / lrun0;
        const float li1 = 1.0f / lrun1;
        const size_t r = (size_t)b * N1 + (size_t)qt * 128 + m0 + g;
        __half* d0 = ao + r * INNER + h * DHEAD;
        __half* d1 = d0 + 8 * INNER;
        #pragma unroll
        for (int nt = 0; nt < 8; nt++) {
            const int cc = 8 * nt + 2 * tg;
            *(uint32_t*)(d0 + cc) = packh2(accO[nt][0] * li0, accO[nt][1] * li0);
            *(uint32_t*)(d1 + cc) = packh2(accO[nt][2] * li1, accO[nt][3] * li1);
        }
    }
}

// ---------------------------------------------------------------------------
// Launch
// ---------------------------------------------------------------------------
extern "C" void kernel_launch(void* const* d_in, const int* in_sizes, int n_in,
                              void* d_out, int out_size)
{
    (void)in_sizes; (void)n_in; (void)out_size;

    const float* x1  = (const float*)d_in[0];
    const float* x2  = (const float*)d_in[1];
    const float* Wq1 = (const float*)d_in[2];
    const float* Wk1 = (const float*)d_in[3];
    const float* Wv1 = (const float*)d_in[4];
    const float* Wk2 = (const float*)d_in[5];
    const float* Wv2 = (const float*)d_in[6];
    const float* Wo  = (const float*)d_in[7];
    const float* bo  = (const float*)d_in[8];
    float* out = (float*)d_out;

    __half *q1, *kbuf, *vbuf, *aobuf, *wt, *xr;
    cudaGetSymbolAddress((void**)&q1,    g_q1);
    cudaGetSymbolAddress((void**)&kbuf,  g_k);
    cudaGetSymbolAddress((void**)&vbuf,  g_v);
    cudaGetSymbolAddress((void**)&aobuf, g_ao);
    cudaGetSymbolAddress((void**)&wt,    g_wt);
    cudaGetSymbolAddress((void**)&xr,    g_xr);

    const int gemm_smem  = 4 * GBUF * (int)sizeof(__half);    // 40960
    const int flash_smem = 2 * FBUF_H * (int)sizeof(__half);  // 36864
    cudaFuncSetAttribute(gemm5,  cudaFuncAttributeMaxDynamicSharedMemorySize, gemm_smem);
    cudaFuncSetAttribute(gemmO,  cudaFuncAttributeMaxDynamicSharedMemorySize, gemm_smem);
    cudaFuncSetAttribute(flash4, cudaFuncAttributeMaxDynamicSharedMemorySize, flash_smem);

    transpose6<<<dim3(32, 32, 6), dim3(32, 8)>>>(Wq1, Wk1, Wv1, Wk2, Wv2, Wo, wt);
    conv_x<<<4096, 256>>>(x1, x2, xr);

    gemm5<<<dim3(INNER / 128, MTOT / 128, 5), 256, gemm_smem>>>(
        xr, xr + (size_t)MTOT * D, wt, q1, kbuf, vbuf);

    flash4<<<dim3(N1 / 128, HEADS, B), 256, flash_smem>>>(q1, kbuf, vbuf, aobuf);

    gemmO<<<dim3(D / 128, MTOT / 128, 1), 256, gemm_smem>>>(aobuf, wt + 5 * WSZ, out, bo);
}

// round 9
// speedup vs baseline: 7.2134x; 1.0664x over previous
#include <cuda_runtime.h>
#include <cuda_fp16.h>
#include <cstddef>
#include <cstdint>

// ---------------------------------------------------------------------------
// Problem constants
// ---------------------------------------------------------------------------
#define B     4
#define N1    2048
#define N2    2048
#define D     1024
#define HEADS 8
#define DHEAD 64
#define INNER (HEADS * DHEAD)     // 512
#define NKV   (N1 + N2)           // 4096
#define MTOT  (B * N1)            // 8192

#define SCALE_Q 0.18033688011112042f   // 0.125 * log2(e)

// Scratch (device globals — no allocation allowed), all fp16
__device__ __half g_q1[(size_t)B * N1 * INNER];
__device__ __half g_k [(size_t)B * NKV * INNER];
__device__ __half g_v [(size_t)B * NKV * INNER];
__device__ __half g_ao[(size_t)B * N1 * INNER];
#define WSZ (1024 * 512)
__device__ __half g_wt[6 * WSZ];                  // transposed weights [N,K]
__device__ __half g_xr[2 * (size_t)MTOT * D];     // converted x1,x2

// ---------------------------------------------------------------------------
// PTX helpers (baseline sm_80-level only — safe for compute_103 target)
// ---------------------------------------------------------------------------
__device__ __forceinline__ uint32_t smem_u32(const void* p) {
    uint32_t a;
    asm("{ .reg .u64 t; cvta.to.shared.u64 t, %1; cvt.u32.u64 %0, t; }"
        : "=r"(a) : "l"(p));
    return a;
}
__device__ __forceinline__ void cpasync16(uint32_t dst, const void* src) {
    asm volatile("cp.async.cg.shared.global [%0], [%1], 16;"
                 :: "r"(dst), "l"(src) : "memory");
}
#define CP_COMMIT() asm volatile("cp.async.commit_group;" ::: "memory")
#define CP_WAIT0()  asm volatile("cp.async.wait_group 0;" ::: "memory")

// f16 mma m16n8k16, f32 accumulate. A row-major (16x16), B col-major (16x8).
__device__ __forceinline__ void mma_f16(float* d, const uint32_t* a, const uint32_t* b) {
    asm volatile(
        "mma.sync.aligned.m16n8k16.row.col.f32.f16.f16.f32 "
        "{%0,%1,%2,%3}, {%4,%5,%6,%7}, {%8,%9}, {%0,%1,%2,%3};"
        : "+f"(d[0]), "+f"(d[1]), "+f"(d[2]), "+f"(d[3])
        : "r"(a[0]), "r"(a[1]), "r"(a[2]), "r"(a[3]), "r"(b[0]), "r"(b[1]));
}

__device__ __forceinline__ void ldmatrix_x4(
    uint32_t& r0, uint32_t& r1, uint32_t& r2, uint32_t& r3, uint32_t addr)
{
    asm volatile("ldmatrix.sync.aligned.m8n8.x4.shared.b16 {%0,%1,%2,%3}, [%4];"
                 : "=r"(r0), "=r"(r1), "=r"(r2), "=r"(r3) : "r"(addr));
}
__device__ __forceinline__ void ldmatrix_x4_trans(
    uint32_t& r0, uint32_t& r1, uint32_t& r2, uint32_t& r3, uint32_t addr)
{
    asm volatile("ldmatrix.sync.aligned.m8n8.x4.trans.shared.b16 {%0,%1,%2,%3}, [%4];"
                 : "=r"(r0), "=r"(r1), "=r"(r2), "=r"(r3) : "r"(addr));
}

__device__ __forceinline__ uint32_t packh2(float x, float y) {
    __half2 h = __floats2half2_rn(x, y);
    return *reinterpret_cast<uint32_t*>(&h);
}
__device__ __forceinline__ uint32_t ldh2(const __half* p) {
    return *reinterpret_cast<const uint32_t*>(p);
}

// ---------------------------------------------------------------------------
// Fused weight transpose + f16 convert: 6 weights -> g_wt (each [N,K])
// ---------------------------------------------------------------------------
__global__ void transpose6(const float* __restrict__ Wq1, const float* __restrict__ Wk1,
                           const float* __restrict__ Wv1, const float* __restrict__ Wk2,
                           const float* __restrict__ Wv2, const float* __restrict__ Wo,
                           __half* __restrict__ wt)
{
    __shared__ float t[32][33];
    const int z = blockIdx.z;
    const float* src = (z == 0) ? Wq1 : (z == 1) ? Wk1 : (z == 2) ? Wv1
                     : (z == 3) ? Wk2 : (z == 4) ? Wv2 : Wo;
    const int R = (z < 5) ? D : INNER;
    const int C = (z < 5) ? INNER : D;
    __half* dst = wt + (size_t)z * WSZ;

    const int bx = blockIdx.x * 32, by = blockIdx.y * 32;
    if (bx >= C || by >= R) return;
    const int x = bx + threadIdx.x;
    for (int i = threadIdx.y; i < 32; i += 8)
        t[i][threadIdx.x] = src[(size_t)(by + i) * C + x];
    __syncthreads();
    const int ox = by + threadIdx.x;
    for (int i = threadIdx.y; i < 32; i += 8)
        dst[(size_t)(bx + i) * R + ox] = __float2half_rn(t[threadIdx.x][i]);
}

// ---------------------------------------------------------------------------
// Convert x1, x2 to f16 into g_xr
// ---------------------------------------------------------------------------
#define XF4 ((size_t)MTOT * D / 4)
__global__ void conv_x(const float* __restrict__ x1, const float* __restrict__ x2,
                       __half* __restrict__ xr)
{
    const size_t total = 2 * XF4;
    for (size_t i = (size_t)blockIdx.x * blockDim.x + threadIdx.x;
         i < total; i += (size_t)gridDim.x * blockDim.x) {
        const float4 v = (i < XF4) ? ((const float4*)x1)[i] : ((const float4*)x2)[i - XF4];
        uint2 o;
        o.x = packh2(v.x, v.y);
        o.y = packh2(v.z, v.w);
        ((uint2*)xr)[i] = o;
    }
}

// ---------------------------------------------------------------------------
// cp.async double-buffered f16 GEMM core (128x128, BK=32, 8 warps)
// Fragments via ldmatrix.x4.  Smem pitch 40 halves (80B row shift).
// ---------------------------------------------------------------------------
#define KP 40
#define GBUF (128 * KP)                 // halves per matrix buffer

__device__ __forceinline__ void gemm_core(
    const __half* __restrict__ A, const __half* __restrict__ Bt,
    void* __restrict__ C, const float* __restrict__ bias,
    int K, int N, size_t cstride, size_t coff, float scale, bool outHalf)
{
    extern __shared__ __half gsm[];

    const int tid = threadIdx.x;
    const int w = tid >> 5, lane = tid & 31;
    const int g = lane >> 2, tg = lane & 3;
    const int wm = (w & 1) * 64, wn = (w >> 1) * 32;
    const int m0 = blockIdx.y * 128, n0 = blockIdx.x * 128;

    const int lr = tid >> 1;
    const int lc = (tid & 1) * 16;     // halves offset: 0 or 16

    const __half* Ag = A  + (size_t)(m0 + lr) * K + lc;
    const __half* Bg = Bt + (size_t)(n0 + lr) * K + lc;

    const uint32_t smb  = smem_u32(gsm);
    const uint32_t dstA = smb + (uint32_t)(lr * KP + lc) * 2;
    const uint32_t dstB = dstA + GBUF * 2;
    const uint32_t BUFB = 2 * GBUF * 2;

    // ldmatrix lane roles
    const int sub = lane >> 3, rw = lane & 7;
    const int a_roff = (sub & 1) * 8, a_koff = (sub >> 1) * 8;   // A frag mapping
    const int b_roff = (sub >> 1) * 8, b_koff = (sub & 1) * 8;   // B frag mapping

    #pragma unroll
    for (int c = 0; c < 2; c++) {
        cpasync16(dstA + 16 * c, Ag + 8 * c);
        cpasync16(dstB + 16 * c, Bg + 8 * c);
    }
    CP_COMMIT();

    float acc[4][4][4] = {};
    const int S = K >> 5;
    for (int s = 0; s < S; s++) {
        CP_WAIT0();
        __syncthreads();
        if (s + 1 < S) {
            const uint32_t off = (uint32_t)((s + 1) & 1) * BUFB;
            const __half* Ag2 = Ag + (s + 1) * 32;
            const __half* Bg2 = Bg + (s + 1) * 32;
            #pragma unroll
            for (int c = 0; c < 2; c++) {
                cpasync16(dstA + off + 16 * c, Ag2 + 8 * c);
                cpasync16(dstB + off + 16 * c, Bg2 + 8 * c);
            }
            CP_COMMIT();
        }
        const uint32_t asb = smb + (uint32_t)((s & 1) * (2 * GBUF)) * 2;
        const uint32_t bsb = asb + GBUF * 2;

        #pragma unroll
        for (int ks = 0; ks < 2; ks++) {          // two k16 slices
            const int k0 = 16 * ks;
            uint32_t af[4][4], bf[4][2];
            #pragma unroll
            for (int mt = 0; mt < 4; mt++) {
                const uint32_t aa = asb +
                    (uint32_t)((wm + 16 * mt + a_roff + rw) * KP + k0 + a_koff) * 2;
                ldmatrix_x4(af[mt][0], af[mt][1], af[mt][2], af[mt][3], aa);
            }
            #pragma unroll
            for (int np = 0; np < 2; np++) {      // nt pairs
                const uint32_t ba = bsb +
                    (uint32_t)((wn + 16 * np + b_roff + rw) * KP + k0 + b_koff) * 2;
                ldmatrix_x4(bf[2 * np][0], bf[2 * np][1],
                            bf[2 * np + 1][0], bf[2 * np + 1][1], ba);
            }
            #pragma unroll
            for (int mt = 0; mt < 4; mt++)
                #pragma unroll
                for (int nt = 0; nt < 4; nt++)
                    mma_f16(acc[mt][nt], af[mt], bf[nt]);
        }
    }

    #pragma unroll
    for (int mt = 0; mt < 4; mt++) {
        const size_t r0 = (size_t)(m0 + wm + 16 * mt + g);
        const size_t r1 = r0 + 8;
        const size_t o0 = (r0 >> 11) * cstride + (r0 & 2047) * N + coff;
        const size_t o1 = (r1 >> 11) * cstride + (r1 & 2047) * N + coff;
        #pragma unroll
        for (int nt = 0; nt < 4; nt++) {
            const int cc = n0 + wn + 8 * nt + 2 * tg;
            float v00 = acc[mt][nt][0] * scale;
            float v01 = acc[mt][nt][1] * scale;
            float v10 = acc[mt][nt][2] * scale;
            float v11 = acc[mt][nt][3] * scale;
            if (outHalf) {
                *(uint32_t*)((__half*)C + o0 + cc) = packh2(v00, v01);
                *(uint32_t*)((__half*)C + o1 + cc) = packh2(v10, v11);
            } else {
                const float bx = bias ? bias[cc] : 0.f;
                const float by = bias ? bias[cc + 1] : 0.f;
                *(float2*)((float*)C + o0 + cc) = make_float2(v00 + bx, v01 + by);
                *(float2*)((float*)C + o1 + cc) = make_float2(v10 + bx, v11 + by);
            }
        }
    }
}

__global__ __launch_bounds__(256, 2)
void gemm5(const __half* __restrict__ x1r, const __half* __restrict__ x2r,
           const __half* __restrict__ wt,
           __half* __restrict__ q1, __half* __restrict__ k, __half* __restrict__ v)
{
    const int z = blockIdx.z;
    const __half* A = (z < 3) ? x1r : x2r;
    const __half* W = wt + (size_t)z * WSZ;
    const size_t kvs  = (size_t)NKV * INNER;
    const size_t off2 = (size_t)N1 * INNER;
    __half* Cp; size_t cs, co; float sc;
    if (z == 0)      { Cp = q1; cs = (size_t)N1 * INNER; co = 0;    sc = SCALE_Q; }
    else if (z == 1) { Cp = k;  cs = kvs;                co = 0;    sc = 1.f; }
    else if (z == 2) { Cp = v;  cs = kvs;                co = 0;    sc = 1.f; }
    else if (z == 3) { Cp = k;  cs = kvs;                co = off2; sc = 1.f; }
    else             { Cp = v;  cs = kvs;                co = off2; sc = 1.f; }
    gemm_core(A, W, Cp, nullptr, D, INNER, cs, co, sc, true);
}

__global__ __launch_bounds__(256, 2)
void gemmO(const __half* __restrict__ ao, const __half* __restrict__ wt5,
           float* __restrict__ out, const float* __restrict__ bo)
{
    gemm_core(ao, wt5, out, bo, INNER, D, (size_t)N1 * D, 0, 1.f, false);
}

// ---------------------------------------------------------------------------
// Flash attention v5: all-f16 MMA, ldmatrix for K and V fragments.
// Block 256 thr (8 warps), q-tile 128 (warp w: rows 16w..16w+16), kv-tile 64.
// K,V f16 in smem pitch 72 halves, double-buffered (36 KB total).
// ---------------------------------------------------------------------------
#define APH 72
#define KV_H   (64 * APH)           // halves per K (or V) tile
#define FBUF_H (2 * KV_H)           // halves per stage (K+V)

__global__ __launch_bounds__(256, 2)
void flash5(const __half* __restrict__ q, const __half* __restrict__ kc,
            const __half* __restrict__ vc, __half* __restrict__ ao)
{
    extern __shared__ __half fsm[];

    const int b  = blockIdx.z;
    const int h  = blockIdx.y;
    const int qt = blockIdx.x;
    const int tid  = threadIdx.x;
    const int w = tid >> 5, lane = tid & 31;
    const int g = lane >> 2, tg = lane & 3;
    const int m0 = 16 * w;

    const __half* qb = q  + ((size_t)b * N1 + (size_t)qt * 128) * INNER + h * DHEAD;
    const __half* kb = kc + (size_t)b * NKV * INNER + h * DHEAD;
    const __half* vb = vc + (size_t)b * NKV * INNER + h * DHEAD;

    const uint32_t smb = smem_u32(fsm);

    const int cr = tid >> 2;
    const int cc0 = (tid & 3) * 16;

    // --- kick off KV tile 0 prefetch ---
    {
        const uint32_t kdst = smb + (uint32_t)(cr * APH + cc0) * 2;
        const uint32_t vdst = kdst + KV_H * 2;
        const __half* ks = kb + (size_t)cr * INNER + cc0;
        const __half* vs = vb + (size_t)cr * INNER + cc0;
        #pragma unroll
        for (int c = 0; c < 2; c++) {
            cpasync16(kdst + 16 * c, ks + 8 * c);
            cpasync16(vdst + 16 * c, vs + 8 * c);
        }
    }
    CP_COMMIT();

    // --- Q A-fragments from gmem (16 regs: 4 k-slices x 4) ---
    uint32_t qaf[4][4];
    {
        const __half* q0 = qb + (size_t)(m0 + g) * INNER;
        const __half* q1r = q0 + 8 * INNER;
        #pragma unroll
        for (int s = 0; s < 4; s++) {
            qaf[s][0] = ldh2(q0  + 16 * s + 2 * tg);
            qaf[s][1] = ldh2(q1r + 16 * s + 2 * tg);
            qaf[s][2] = ldh2(q0  + 16 * s + 2 * tg + 8);
            qaf[s][3] = ldh2(q1r + 16 * s + 2 * tg + 8);
        }
    }

    float accO[8][4] = {};
    float mrun0 = -1e30f, mrun1 = -1e30f, lrun0 = 0.f, lrun1 = 0.f;

    // ldmatrix lane roles
    const int sub = lane >> 3, rw = lane & 7;
    const int k_roff = (sub >> 1) * 8, k_koff = (sub & 1) * 8;   // K B-frag mapping
    const int vmat = sub;
    const int vr = (vmat & 1) * 8 + rw;       // V trans: row within 16-kv slice
    const int vcb = (vmat >> 1) * 8;          // V trans: col offset in 16-d pair

    const int NT = NKV / 64;
    for (int j = 0; j < NT; j++) {
        CP_WAIT0();
        __syncthreads();

        if (j + 1 < NT) {
            const uint32_t base = smb + (uint32_t)(((j + 1) & 1) * FBUF_H) * 2;
            const uint32_t kdst = base + (uint32_t)(cr * APH + cc0) * 2;
            const uint32_t vdst = kdst + KV_H * 2;
            const __half* ks = kb + (size_t)(j + 1) * 64 * INNER + (size_t)cr * INNER + cc0;
            const __half* vs = vb + (size_t)(j + 1) * 64 * INNER + (size_t)cr * INNER + cc0;
            #pragma unroll
            for (int c = 0; c < 2; c++) {
                cpasync16(kdst + 16 * c, ks + 8 * c);
                cpasync16(vdst + 16 * c, vs + 8 * c);
            }
            CP_COMMIT();
        }

        const uint32_t ksb = smb + (uint32_t)((j & 1) * FBUF_H) * 2;
        const uint32_t vsb = ksb + KV_H * 2;

        // --- S = Q @ K^T (warp: 16x64): ldmatrix.x4 B-frags, 32 f16 MMAs ---
        float sacc[8][4] = {};
        #pragma unroll
        for (int ks = 0; ks < 4; ks++) {
            const int k0 = 16 * ks;
            #pragma unroll
            for (int np = 0; np < 4; np++) {      // nt pairs
                uint32_t b0, b1, b2, b3;
                const uint32_t ka = ksb +
                    (uint32_t)((16 * np + k_roff + rw) * APH + k0 + k_koff) * 2;
                ldmatrix_x4(b0, b1, b2, b3, ka);
                uint32_t bf0[2] = { b0, b1 };
                uint32_t bf1[2] = { b2, b3 };
                mma_f16(sacc[2 * np],     qaf[ks], bf0);
                mma_f16(sacc[2 * np + 1], qaf[ks], bf1);
            }
        }

        // --- register online softmax ---
        float rm0 = -1e30f, rm1 = -1e30f;
        #pragma unroll
        for (int nt = 0; nt < 8; nt++) {
            rm0 = fmaxf(rm0, fmaxf(sacc[nt][0], sacc[nt][1]));
            rm1 = fmaxf(rm1, fmaxf(sacc[nt][2], sacc[nt][3]));
        }
        #pragma unroll
        for (int off = 1; off <= 2; off <<= 1) {
            rm0 = fmaxf(rm0, __shfl_xor_sync(0xFFFFFFFFu, rm0, off));
            rm1 = fmaxf(rm1, __shfl_xor_sync(0xFFFFFFFFu, rm1, off));
        }
        const float mn0 = fmaxf(mrun0, rm0);
        const float mn1 = fmaxf(mrun1, rm1);
        const float al0 = exp2f(mrun0 - mn0);
        const float al1 = exp2f(mrun1 - mn1);

        float rs0 = 0.f, rs1 = 0.f;
        uint32_t paf[4][4];                  // P A-frags, packed while exping
        #pragma unroll
        for (int ks = 0; ks < 4; ks++) {
            const int e0 = 2 * ks, e1 = 2 * ks + 1;
            float p00 = exp2f(sacc[e0][0] - mn0);
            float p01 = exp2f(sacc[e0][1] - mn0);
            float p10 = exp2f(sacc[e0][2] - mn1);
            float p11 = exp2f(sacc[e0][3] - mn1);
            float p20 = exp2f(sacc[e1][0] - mn0);
            float p21 = exp2f(sacc[e1][1] - mn0);
            float p30 = exp2f(sacc[e1][2] - mn1);
            float p31 = exp2f(sacc[e1][3] - mn1);
            rs0 += p00 + p01 + p20 + p21;
            rs1 += p10 + p11 + p30 + p31;
            paf[ks][0] = packh2(p00, p01);
            paf[ks][1] = packh2(p10, p11);
            paf[ks][2] = packh2(p20, p21);
            paf[ks][3] = packh2(p30, p31);
        }
        #pragma unroll
        for (int off = 1; off <= 2; off <<= 1) {
            rs0 += __shfl_xor_sync(0xFFFFFFFFu, rs0, off);
            rs1 += __shfl_xor_sync(0xFFFFFFFFu, rs1, off);
        }
        lrun0 = lrun0 * al0 + rs0;
        lrun1 = lrun1 * al1 + rs1;
        mrun0 = mn0;
        mrun1 = mn1;

        // rescale O only if some row max changed anywhere in the warp
        if (!__all_sync(0xFFFFFFFFu, (al0 == 1.f) && (al1 == 1.f))) {
            #pragma unroll
            for (int nt = 0; nt < 8; nt++) {
                accO[nt][0] *= al0; accO[nt][1] *= al0;
                accO[nt][2] *= al1; accO[nt][3] *= al1;
            }
        }

        // --- O += P @ V : ldmatrix.x4.trans B-frags, 32 f16 MMAs ---
        #pragma unroll
        for (int ks = 0; ks < 4; ks++) {
            #pragma unroll
            for (int dp = 0; dp < 4; dp++) {
                uint32_t r0, r1, r2, r3;
                const uint32_t addr = vsb +
                    (uint32_t)((16 * ks + vr) * APH + 16 * dp + vcb) * 2;
                ldmatrix_x4_trans(r0, r1, r2, r3, addr);
                uint32_t bf0[2] = { r0, r1 };
                uint32_t bf1[2] = { r2, r3 };
                mma_f16(accO[2 * dp],     paf[ks], bf0);
                mma_f16(accO[2 * dp + 1], paf[ks], bf1);
            }
        }
    }

    // --- normalize + write f16 ---
    {
        const float li0 = 1.0f / lrun0;
        const float li1 = 1.0f / lrun1;
        const size_t r = (size_t)b * N1 + (size_t)qt * 128 + m0 + g;
        __half* d0 = ao + r * INNER + h * DHEAD;
        __half* d1 = d0 + 8 * INNER;
        #pragma unroll
        for (int nt = 0; nt < 8; nt++) {
            const int cc = 8 * nt + 2 * tg;
            *(uint32_t*)(d0 + cc) = packh2(accO[nt][0] * li0, accO[nt][1] * li0);
            *(uint32_t*)(d1 + cc) = packh2(accO[nt][2] * li1, accO[nt][3] * li1);
        }
    }
}

// ---------------------------------------------------------------------------
// Launch
// ---------------------------------------------------------------------------
extern "C" void kernel_launch(void* const* d_in, const int* in_sizes, int n_in,
                              void* d_out, int out_size)
{
    (void)in_sizes; (void)n_in; (void)out_size;

    const float* x1  = (const float*)d_in[0];
    const float* x2  = (const float*)d_in[1];
    const float* Wq1 = (const float*)d_in[2];
    const float* Wk1 = (const float*)d_in[3];
    const float* Wv1 = (const float*)d_in[4];
    const float* Wk2 = (const float*)d_in[5];
    const float* Wv2 = (const float*)d_in[6];
    const float* Wo  = (const float*)d_in[7];
    const float* bo  = (const float*)d_in[8];
    float* out = (float*)d_out;

    __half *q1, *kbuf, *vbuf, *aobuf, *wt, *xr;
    cudaGetSymbolAddress((void**)&q1,    g_q1);
    cudaGetSymbolAddress((void**)&kbuf,  g_k);
    cudaGetSymbolAddress((void**)&vbuf,  g_v);
    cudaGetSymbolAddress((void**)&aobuf, g_ao);
    cudaGetSymbolAddress((void**)&wt,    g_wt);
    cudaGetSymbolAddress((void**)&xr,    g_xr);

    const int gemm_smem  = 4 * GBUF * (int)sizeof(__half);    // 40960
    const int flash_smem = 2 * FBUF_H * (int)sizeof(__half);  // 36864
    cudaFuncSetAttribute(gemm5,  cudaFuncAttributeMaxDynamicSharedMemorySize, gemm_smem);
    cudaFuncSetAttribute(gemmO,  cudaFuncAttributeMaxDynamicSharedMemorySize, gemm_smem);
    cudaFuncSetAttribute(flash5, cudaFuncAttributeMaxDynamicSharedMemorySize, flash_smem);

    transpose6<<<dim3(32, 32, 6), dim3(32, 8)>>>(Wq1, Wk1, Wv1, Wk2, Wv2, Wo, wt);
    conv_x<<<4096, 256>>>(x1, x2, xr);

    gemm5<<<dim3(INNER / 128, MTOT / 128, 5), 256, gemm_smem>>>(
        xr, xr + (size_t)MTOT * D, wt, q1, kbuf, vbuf);

    flash5<<<dim3(N1 / 128, HEADS, B), 256, flash_smem>>>(q1, kbuf, vbuf, aobuf);

    gemmO<<<dim3(D / 128, MTOT / 128, 1), 256, gemm_smem>>>(aobuf, wt + 5 * WSZ, out, bo);
}